// round 12
// baseline (speedup 1.0000x reference)
#include <cuda_runtime.h>
#include <cuda_fp16.h>
#include <math.h>
#include <stdint.h>

#define BATCH 4
#define T 2048
#define DM 512
#define DI 1024
#define NH 16
#define HD 64
#define DS 16
#define CONVD 1056
#define DPROJ 2096
#define DINTER 256
#define ROWS (BATCH*T)

// chunked scan
#define CQ 64
#define NC (T/CQ)

// fp16 GEMM tiling: block 128(M) x 256(N), BK=64 halves, 4 stages
#define BKH 64
#define LDA 72                      // halves per smem row (144 B)
#define A_ST_BYTES (128*144)
#define B_ST_BYTES (256*144)
#define ST_BYTES (A_ST_BYTES+B_ST_BYTES)   // 55296
#define STG 4
#define GEMM_SMEM (STG*ST_BYTES)    // 221184

// ---------------- scratch ----------------
__device__ float g_resid[ROWS*DM];
__device__ __half g_hh[ROWS*DM];          // LN output (fp16, GEMM A)
__device__ __half g_zx[ROWS*DPROJ];       // in_proj output (fp16)
__device__ float g_y[ROWS*DI];
__device__ __half g_yh[ROWS*DI];
__device__ float g_tmp[ROWS*DM];
__device__ __half g_gluh[ROWS*DINTER];
__device__ float g_x[ROWS*DM];
__device__ float g_sloc[BATCH*NH*NC*HD*DS];
__device__ float g_hinit[BATCH*NH*NC*HD*DS];
__device__ float g_cdecay[BATCH*NH*NC];
// fp16 weights
__device__ __half g_winw[4*DPROJ*DM];
__device__ __half g_wow[4*DM*DI];
__device__ __half g_wf1[4*2*DINTER*DM];
__device__ __half g_wf2[4*DM*DINTER];

// ---------------- weight conversion ----------------
__global__ void conv_copy_h(const float* __restrict__ src, __half* __restrict__ dst, int n4) {
    int i = blockIdx.x * blockDim.x + threadIdx.x;
    if (i >= n4) return;
    float4 v = ((const float4*)src)[i];
    ((__half2*)dst)[2 * i]     = __floats2half2_rn(v.x, v.y);
    ((__half2*)dst)[2 * i + 1] = __floats2half2_rn(v.z, v.w);
}

__global__ void conv_interleave_f1_h(const float* __restrict__ src, __half* __restrict__ dst) {
    int i = blockIdx.x * blockDim.x + threadIdx.x;
    int total4 = 4 * 512 * 512 / 4;
    if (i >= total4) return;
    int k4 = i & 127;
    int row = (i >> 7) & 511;
    int l = i >> 16;
    float4 v = ((const float4*)src)[i];
    int drow = (row < 256) ? (2 * row) : (2 * (row - 256) + 1);
    size_t o = (((size_t)l * 512 + drow) * 512 + k4 * 4);
    ((__half2*)(dst + o))[0] = __floats2half2_rn(v.x, v.y);
    ((__half2*)(dst + o))[1] = __floats2half2_rn(v.z, v.w);
}

// ---------------- residual add + LayerNorm ----------------
__global__ void add_ln_kernel(const float* __restrict__ xin, float* __restrict__ resid,
                              const float* __restrict__ w, const float* __restrict__ bch,
                              void* __restrict__ out, int first, int to_half) {
    int row = blockIdx.x;
    const float* xr = xin + (size_t)row * DM;
    float* rr = resid + (size_t)row * DM;
    int tid = threadIdx.x;
    float v[4]; float s = 0.f, s2 = 0.f;
#pragma unroll
    for (int j = 0; j < 4; j++) {
        int c = tid + j * 128;
        float val = xr[c];
        if (!first) val += rr[c];
        v[j] = val; s += val; s2 += val * val;
    }
#pragma unroll
    for (int o = 16; o > 0; o >>= 1) {
        s  += __shfl_xor_sync(0xffffffffu, s, o);
        s2 += __shfl_xor_sync(0xffffffffu, s2, o);
    }
    __shared__ float rs[4], rs2[4];
    int wid = tid >> 5;
    if ((tid & 31) == 0) { rs[wid] = s; rs2[wid] = s2; }
    __syncthreads();
    float tot  = rs[0] + rs[1] + rs[2] + rs[3];
    float tot2 = rs2[0] + rs2[1] + rs2[2] + rs2[3];
    float mu = tot * (1.f / DM);
    float var = tot2 * (1.f / DM) - mu * mu;
    float inv = rsqrtf(var + 1e-5f);
#pragma unroll
    for (int j = 0; j < 4; j++) {
        int c = tid + j * 128;
        float val = v[j];
        rr[c] = val;
        float o2 = (val - mu) * inv * w[c] + bch[c];
        if (to_half) ((__half*)out)[(size_t)row * DM + c] = __float2half_rn(o2);
        else         ((float*)out)[(size_t)row * DM + c] = o2;
    }
}

// ---------------- fp16 tensor-core NT GEMM (128x256 block, 4-stage, 1 sync/iter) ----------------
#define MMA_F16(d, a, b) \
    asm volatile("mma.sync.aligned.m16n8k16.row.col.f32.f16.f16.f32 " \
                 "{%0,%1,%2,%3},{%4,%5,%6,%7},{%8,%9},{%0,%1,%2,%3};" \
                 : "+f"(d[0]), "+f"(d[1]), "+f"(d[2]), "+f"(d[3]) \
                 : "r"(a[0]), "r"(a[1]), "r"(a[2]), "r"(a[3]), "r"(b[0]), "r"(b[1]))

#define LDSM_X4(R, addr) \
    asm volatile("ldmatrix.sync.aligned.m8n8.x4.shared.b16 {%0,%1,%2,%3}, [%4];" \
                 : "=r"((R)[0]), "=r"((R)[1]), "=r"((R)[2]), "=r"((R)[3]) : "r"(addr))

__device__ __forceinline__ void gemm_load_stage(
    const __half* __restrict__ A, const __half* __restrict__ Bw,
    int K, int N, int bm, int bn, int it, int s, int tid, uint32_t sbase)
{
    int k0 = it * BKH;
    uint32_t stA = sbase + (uint32_t)s * ST_BYTES;
    uint32_t stB = stA + A_ST_BYTES;
#pragma unroll
    for (int i = 0; i < 4; i++) {
        int idx = i * 256 + tid;
        int row = idx >> 3, c = idx & 7;
        uint32_t dst = stA + (uint32_t)row * 144u + (uint32_t)(c << 4);
        const __half* gp = A + (size_t)(bm + row) * K + k0 + c * 8;
        asm volatile("cp.async.cg.shared.global [%0], [%1], 16;" :: "r"(dst), "l"(gp));
    }
#pragma unroll
    for (int i = 0; i < 8; i++) {
        int idx = i * 256 + tid;
        int row = idx >> 3, c = idx & 7;
        int rb = bn + row;
        int valid = (rb < N);
        uint32_t dst = stB + (uint32_t)row * 144u + (uint32_t)(c << 4);
        const __half* gp = Bw + (size_t)(valid ? rb : 0) * K + k0 + c * 8;
        int ssz = valid ? 16 : 0;
        asm volatile("cp.async.cg.shared.global [%0], [%1], 16, %2;" :: "r"(dst), "l"(gp), "r"(ssz));
    }
    asm volatile("cp.async.commit_group;" ::: "memory");
}

// out_mode: 0 = fp32 C, 1 = fused GLU (fp16, N/2 cols), 2 = fp16 C
__global__ void __launch_bounds__(256) h16_gemm_nt(int M, int N, int K,
                                                   const __half* __restrict__ A,
                                                   const __half* __restrict__ Bw,
                                                   void* __restrict__ Cv, int out_mode) {
    extern __shared__ char smem[];
    uint32_t sbase = (uint32_t)__cvta_generic_to_shared(smem);
    int bm = blockIdx.y * 128, bn = blockIdx.x * 256;
    int tid = threadIdx.x;
    int wid = tid >> 5, lane = tid & 31;
    int wm = (wid & 1) * 64;
    int wn = (wid >> 1) * 64;
    int g = lane >> 2, tig = lane & 3;

    int arow = lane & 15;
    int acol = (lane >> 4) << 3;
    int brow = ((lane >> 4) << 3) + (lane & 7);
    int bcol = ((lane >> 3) & 1) << 3;
    uint32_t aoff = ((uint32_t)((wm + arow) * LDA + acol)) * 2u;
    uint32_t boff = ((uint32_t)((wn + brow) * LDA + bcol)) * 2u + A_ST_BYTES;

    float acc[4][8][4];
#pragma unroll
    for (int i = 0; i < 4; i++)
#pragma unroll
        for (int j = 0; j < 8; j++)
#pragma unroll
            for (int k = 0; k < 4; k++) acc[i][j][k] = 0.f;

    int NIT = K / BKH;
#pragma unroll
    for (int p = 0; p < STG - 1; p++)
        if (p < NIT) gemm_load_stage(A, Bw, K, N, bm, bn, p, p, tid, sbase);

    for (int it = 0; it < NIT; ++it) {
        int pend = NIT - it - 1; if (pend > STG - 2) pend = STG - 2;
        if (pend == 2)      asm volatile("cp.async.wait_group 2;" ::: "memory");
        else if (pend == 1) asm volatile("cp.async.wait_group 1;" ::: "memory");
        else                asm volatile("cp.async.wait_group 0;" ::: "memory");
        __syncthreads();

        int ld = it + STG - 1;
        if (ld < NIT) gemm_load_stage(A, Bw, K, N, bm, bn, ld, ld % STG, tid, sbase);

        int s = it % STG;
        uint32_t Ab = sbase + (uint32_t)s * ST_BYTES + aoff;
        uint32_t Bb = sbase + (uint32_t)s * ST_BYTES + boff;
#pragma unroll
        for (int ks = 0; ks < 4; ks++) {
            uint32_t kbyte = (uint32_t)(ks * 16 * 2);
            uint32_t a[4][4], b[4][4];
#pragma unroll
            for (int mt = 0; mt < 4; mt++)
                LDSM_X4(a[mt], Ab + (uint32_t)(mt * 16 * LDA) * 2u + kbyte);
#pragma unroll
            for (int np = 0; np < 4; np++)
                LDSM_X4(b[np], Bb + (uint32_t)(np * 16 * LDA) * 2u + kbyte);
#pragma unroll
            for (int mt = 0; mt < 4; mt++)
#pragma unroll
                for (int np = 0; np < 4; np++) {
                    MMA_F16(acc[mt][2 * np], a[mt], b[np]);
                    uint32_t bhi[2] = { b[np][2], b[np][3] };
                    MMA_F16(acc[mt][2 * np + 1], a[mt], bhi);
                }
        }
    }

    if (out_mode == 0) {
        float* C = (float*)Cv;
#pragma unroll
        for (int mt = 0; mt < 4; mt++) {
            int r0 = bm + wm + mt * 16 + g;
#pragma unroll
            for (int nt = 0; nt < 8; nt++) {
                int c0 = bn + wn + nt * 8 + tig * 2;
                if (c0 < N) {
                    *(float2*)&C[(size_t)r0 * N + c0] = make_float2(acc[mt][nt][0], acc[mt][nt][1]);
                    *(float2*)&C[(size_t)(r0 + 8) * N + c0] = make_float2(acc[mt][nt][2], acc[mt][nt][3]);
                }
            }
        }
    } else if (out_mode == 2) {
        __half* C = (__half*)Cv;
#pragma unroll
        for (int mt = 0; mt < 4; mt++) {
            int r0 = bm + wm + mt * 16 + g;
#pragma unroll
            for (int nt = 0; nt < 8; nt++) {
                int c0 = bn + wn + nt * 8 + tig * 2;
                if (c0 < N) {
                    *(__half2*)&C[(size_t)r0 * N + c0] = __floats2half2_rn(acc[mt][nt][0], acc[mt][nt][1]);
                    *(__half2*)&C[(size_t)(r0 + 8) * N + c0] = __floats2half2_rn(acc[mt][nt][2], acc[mt][nt][3]);
                }
            }
        }
    } else {
        __half* C = (__half*)Cv;
        int No = N >> 1;
#pragma unroll
        for (int mt = 0; mt < 4; mt++) {
            int r0 = bm + wm + mt * 16 + g;
#pragma unroll
            for (int nt = 0; nt < 8; nt++) {
                int c0 = bn + wn + nt * 8 + tig * 2;
                if (c0 < N) {
                    float a0 = acc[mt][nt][0], g0 = acc[mt][nt][1];
                    float a1 = acc[mt][nt][2], g1 = acc[mt][nt][3];
                    C[(size_t)r0 * No + (c0 >> 1)] = __float2half_rn(a0 * g0 / (1.f + expf(-g0)));
                    C[(size_t)(r0 + 8) * No + (c0 >> 1)] = __float2half_rn(a1 * g1 / (1.f + expf(-g1)));
                }
            }
        }
    }
}

// ---------------- fused conv helpers (scan-coordinate stencil) ----------------
// xBC channel index for tile channel ch (0..63 = X slice of this head, 64..79 = B, 80..95 = C)
__device__ __forceinline__ int xbc_chan(int ch, int head) {
    if (ch < 64) return head * HD + ch;
    if (ch < 80) return 1024 + (ch - 64);
    return 1024 + DS + (ch - 80);
}

// ---------------- chunked SSD scan, conv fused (S1: 80 channels) ----------------
__global__ void __launch_bounds__(256) chunk_state_kernel(
    const __half* __restrict__ zx, const float* __restrict__ cw,
    const float* __restrict__ cb, const float* __restrict__ dtb,
    const float* __restrict__ alog, float* __restrict__ sloc,
    float* __restrict__ cdecay, int rev)
{
    int c = blockIdx.x, head = blockIdx.y, b = blockIdx.z;
    int tid = threadIdx.x;
    __shared__ float Xs[CQ][HD + 4];
    __shared__ float Bs[CQ][DS + 1];
    __shared__ float Ls[CQ];
    __shared__ float wdt[CQ];
    __shared__ __half th[67][80];
    __shared__ float wconv[80][4];
    __shared__ float cbs[80];
    size_t tbase = (size_t)b * T;
    float A = -expf(alog[head]);

    // conv weights for this block's 80 channels
    for (int i = tid; i < 80; i += 256) {
        int chan = xbc_chan(i, head);
        *(float4*)wconv[i] = *(const float4*)(cw + chan * 4);
        cbs[i] = cb[chan];
    }
    // zx tile: 67 scan rows (3 halo + 64) x 80 channels
    for (int i = tid; i < 67 * 80; i += 256) {
        int r = i / 80, ch = i % 80;
        int sp = c * CQ - 3 + r;
        __half v = __float2half(0.f);
        if (sp >= 0) {
            int t = rev ? (T - 1 - sp) : sp;
            v = zx[(tbase + t) * DPROJ + DI + xbc_chan(ch, head)];
        }
        th[r][ch] = v;
    }
    if (tid < CQ) {
        int s = c * CQ + tid;
        int t = rev ? (T - 1 - s) : s;
        float raw = __half2float(zx[(tbase + t) * DPROJ + (DI + CONVD) + head]) + dtb[head];
        float d = (raw > 20.f) ? raw : log1pf(expf(raw));
        wdt[tid] = d;
        Ls[tid] = d * A;
    }
    __syncthreads();

    // conv + silu -> Xs / Bs
    for (int i = tid; i < CQ * 80; i += 256) {
        int j = i / 80, ch = i % 80;
        float acc = cbs[ch];
#pragma unroll
        for (int k = 0; k < 4; k++) acc += wconv[ch][k] * __half2float(th[j + k][ch]);
        float val = acc / (1.f + expf(-acc));
        if (ch < 64) Xs[j][ch] = val; else Bs[j][ch - 64] = val;
    }
    __syncthreads();

    for (int off = 1; off < CQ; off <<= 1) {
        float v = 0.f;
        if (tid < CQ) v = Ls[tid] + ((tid >= off) ? Ls[tid - off] : 0.f);
        __syncthreads();
        if (tid < CQ) Ls[tid] = v;
        __syncthreads();
    }
    float Lend = Ls[CQ - 1];

    int p = tid >> 2, ng = (tid & 3) << 2;
    float acc0 = 0.f, acc1 = 0.f, acc2 = 0.f, acc3 = 0.f;
    for (int j = 0; j < CQ; j++) {
        float w = expf(Lend - Ls[j]) * wdt[j];
        float xv = w * Xs[j][p];
        acc0 += xv * Bs[j][ng + 0];
        acc1 += xv * Bs[j][ng + 1];
        acc2 += xv * Bs[j][ng + 2];
        acc3 += xv * Bs[j][ng + 3];
    }
    size_t o = ((((size_t)b * NH + head) * NC + c) * HD + p) * DS + ng;
    sloc[o + 0] = acc0; sloc[o + 1] = acc1; sloc[o + 2] = acc2; sloc[o + 3] = acc3;
    if (tid == 0) cdecay[((size_t)b * NH + head) * NC + c] = expf(Lend);
}

__global__ void __launch_bounds__(256) chunk_scan_state(
    const float* __restrict__ sloc, const float* __restrict__ cdecay,
    float* __restrict__ hinit)
{
    int bh = blockIdx.x;
    int tid = threadIdx.x;
    float h0 = 0.f, h1 = 0.f, h2 = 0.f, h3 = 0.f;
    for (int c = 0; c < NC; c++) {
        size_t base = ((size_t)bh * NC + c) * (HD * DS);
        float d = cdecay[(size_t)bh * NC + c];
        size_t i0 = base + tid, i1 = base + tid + 256, i2 = base + tid + 512, i3 = base + tid + 768;
        hinit[i0] = h0; hinit[i1] = h1; hinit[i2] = h2; hinit[i3] = h3;
        h0 = d * h0 + sloc[i0];
        h1 = d * h1 + sloc[i1];
        h2 = d * h2 + sloc[i2];
        h3 = d * h3 + sloc[i3];
    }
}

// ---------------- S3: conv fused (96 channels), tile overlaid on Ss ----------------
__global__ void __launch_bounds__(256) chunk_output_kernel(
    const __half* __restrict__ zx, const float* __restrict__ cw,
    const float* __restrict__ cb, const float* __restrict__ dtb,
    const float* __restrict__ alog, const float* __restrict__ hinit,
    const float* __restrict__ Dp, float* __restrict__ y, int rev)
{
    int c = blockIdx.x, head = blockIdx.y, b = blockIdx.z;
    int tid = threadIdx.x;
    __shared__ float Xs[CQ][HD + 4];
    __shared__ float Bs[CQ][DS + 1];
    __shared__ float Cs[CQ][DS + 1];
    __shared__ float h0s[HD][DS + 1];
    __shared__ float Ls[CQ];
    __shared__ float wdt[CQ];
    __shared__ float Ss[CQ][CQ + 1];    // 16640 B; front part doubles as conv tile
    // overlay: th = 67x96 halves (12864 B), wconv = 96x4 floats (1536 B), cbs = 96 floats (384 B)
    __half* th = (__half*)&Ss[0][0];
    float* wconv = (float*)((char*)&Ss[0][0] + 12864);
    float* cbs   = (float*)((char*)&Ss[0][0] + 12864 + 1536);
    size_t tbase = (size_t)b * T;
    float A = -expf(alog[head]);

    for (int i = tid; i < 96; i += 256) {
        int chan = xbc_chan(i, head);
        *(float4*)(wconv + i * 4) = *(const float4*)(cw + chan * 4);
        cbs[i] = cb[chan];
    }
    for (int i = tid; i < 67 * 96; i += 256) {
        int r = i / 96, ch = i % 96;
        int sp = c * CQ - 3 + r;
        __half v = __float2half(0.f);
        if (sp >= 0) {
            int t = rev ? (T - 1 - sp) : sp;
            v = zx[(tbase + t) * DPROJ + DI + xbc_chan(ch, head)];
        }
        th[r * 96 + ch] = v;
    }
    {
        size_t hb = ((((size_t)b * NH + head) * NC + c) * HD) * DS;
        for (int i = tid; i < HD * DS; i += 256) {
            int p = i >> 4, n = i & 15;
            h0s[p][n] = hinit[hb + i];
        }
    }
    if (tid < CQ) {
        int s = c * CQ + tid;
        int t = rev ? (T - 1 - s) : s;
        float raw = __half2float(zx[(tbase + t) * DPROJ + (DI + CONVD) + head]) + dtb[head];
        float d = (raw > 20.f) ? raw : log1pf(expf(raw));
        wdt[tid] = d;
        Ls[tid] = d * A;
    }
    __syncthreads();

    // conv + silu -> Xs / Bs / Cs
    for (int i = tid; i < CQ * 96; i += 256) {
        int j = i / 96, ch = i % 96;
        float acc = cbs[ch];
#pragma unroll
        for (int k = 0; k < 4; k++) acc += wconv[ch * 4 + k] * __half2float(th[(j + k) * 96 + ch]);
        float val = acc / (1.f + expf(-acc));
        if (ch < 64)      Xs[j][ch] = val;
        else if (ch < 80) Bs[j][ch - 64] = val;
        else              Cs[j][ch - 80] = val;
    }
    __syncthreads();   // tile reads done; Ss region reusable below

    for (int off = 1; off < CQ; off <<= 1) {
        float v = 0.f;
        if (tid < CQ) v = Ls[tid] + ((tid >= off) ? Ls[tid - off] : 0.f);
        __syncthreads();
        if (tid < CQ) Ls[tid] = v;
        __syncthreads();
    }

    int t = tid >> 2;
    int quad = tid & 3;
    float Ct[DS];
#pragma unroll
    for (int n = 0; n < DS; n++) Ct[n] = Cs[t][n];
    float Lt = Ls[t];

    int jb = quad * 16;
#pragma unroll
    for (int q = 0; q < 16; q++) {
        int j = jb + q;
        float sv = 0.f;
        if (j <= t) {
            float dot = 0.f;
#pragma unroll
            for (int n = 0; n < DS; n++) dot += Ct[n] * Bs[j][n];
            sv = expf(Lt - Ls[j]) * wdt[j] * dot;
        }
        Ss[t][j] = sv;
    }
    __syncthreads();

    int pb = quad * 16;
    float acc[16];
#pragma unroll
    for (int k = 0; k < 16; k++) acc[k] = 0.f;
    for (int j = 0; j <= t; j++) {
        float sv = Ss[t][j];
#pragma unroll
        for (int k4 = 0; k4 < 4; k4++) {
            float4 xv = *(const float4*)&Xs[j][pb + k4 * 4];
            acc[k4 * 4 + 0] += sv * xv.x;
            acc[k4 * 4 + 1] += sv * xv.y;
            acc[k4 * 4 + 2] += sv * xv.z;
            acc[k4 * 4 + 3] += sv * xv.w;
        }
    }
    float et = expf(Lt);
    float Dv = Dp[head];
#pragma unroll
    for (int k = 0; k < 16; k++) {
        int p = pb + k;
        float dot = 0.f;
#pragma unroll
        for (int n = 0; n < DS; n++) dot += Ct[n] * h0s[p][n];
        acc[k] += et * dot + Dv * Xs[t][p];
    }
    int s_idx = c * CQ + t;
    int trow = rev ? (T - 1 - s_idx) : s_idx;
    float* yr = y + (tbase + trow) * DI + head * HD + pb;
#pragma unroll
    for (int k4 = 0; k4 < 4; k4++) {
        *(float4*)(yr + k4 * 4) = make_float4(acc[k4 * 4 + 0], acc[k4 * 4 + 1], acc[k4 * 4 + 2], acc[k4 * 4 + 3]);
    }
}

// ---------------- y = y * silu(z); RMSNorm(y) * gw -> fp16 ----------------
__global__ void gate_rms(const __half* __restrict__ zx, const float* __restrict__ y,
                         const float* __restrict__ gw, __half* __restrict__ yh) {
    int row = blockIdx.x;
    const __half* z = zx + (size_t)row * DPROJ;
    const float* yr = y + (size_t)row * DI;
    __half* yo = yh + (size_t)row * DI;
    int tid = threadIdx.x;
    float v[4]; float s2 = 0.f;
#pragma unroll
    for (int j = 0; j < 4; j++) {
        int c = tid + j * 256;
        float zz = __half2float(z[c]);
        float val = yr[c] * (zz / (1.f + expf(-zz)));
        v[j] = val; s2 += val * val;
    }
#pragma unroll
    for (int o = 16; o > 0; o >>= 1) s2 += __shfl_xor_sync(0xffffffffu, s2, o);
    __shared__ float rs[8];
    int wid = tid >> 5;
    if ((tid & 31) == 0) rs[wid] = s2;
    __syncthreads();
    float tot = 0.f;
#pragma unroll
    for (int i = 0; i < 8; i++) tot += rs[i];
    float inv = rsqrtf(tot * (1.f / DI) + 1e-5f);
#pragma unroll
    for (int j = 0; j < 4; j++) {
        int c = tid + j * 256;
        yo[c] = __float2half_rn(v[j] * inv * gw[c]);
    }
}

// ---------------- host ----------------
static void* sym_addr_v(const void* sym) {
    void* p = nullptr;
    cudaGetSymbolAddress(&p, sym);
    return p;
}

extern "C" void kernel_launch(void* const* d_in, const int* in_sizes, int n_in,
                              void* d_out, int out_size) {
    const float* in_x   = (const float*)d_in[0];
    const float* n1w    = (const float*)d_in[1];
    const float* n1b    = (const float*)d_in[2];
    const float* inw    = (const float*)d_in[3];
    const float* cw     = (const float*)d_in[4];
    const float* cb     = (const float*)d_in[5];
    const float* dtb    = (const float*)d_in[6];
    const float* alog   = (const float*)d_in[7];
    const float* Dp     = (const float*)d_in[8];
    const float* gw     = (const float*)d_in[9];
    const float* ow     = (const float*)d_in[10];
    const float* n2w    = (const float*)d_in[11];
    const float* n2b    = (const float*)d_in[12];
    const float* f1w    = (const float*)d_in[13];
    const float* f2w    = (const float*)d_in[14];
    const float* nfw    = (const float*)d_in[15];
    const float* nfb    = (const float*)d_in[16];

    float*  resid = (float*) sym_addr_v(g_resid);
    __half* hh    = (__half*)sym_addr_v(g_hh);
    __half* zx    = (__half*)sym_addr_v(g_zx);
    float*  ybuf  = (float*) sym_addr_v(g_y);
    __half* yh    = (__half*)sym_addr_v(g_yh);
    float*  tmp   = (float*) sym_addr_v(g_tmp);
    __half* gluh  = (__half*)sym_addr_v(g_gluh);
    float*  xb    = (float*) sym_addr_v(g_x);
    float*  sloc  = (float*) sym_addr_v(g_sloc);
    float*  hinit = (float*) sym_addr_v(g_hinit);
    float*  cdec  = (float*) sym_addr_v(g_cdecay);
    __half* winw  = (__half*)sym_addr_v(g_winw);
    __half* wow   = (__half*)sym_addr_v(g_wow);
    __half* wf1   = (__half*)sym_addr_v(g_wf1);
    __half* wf2   = (__half*)sym_addr_v(g_wf2);

    static int smem_set = 0;
    if (!smem_set) {
        cudaFuncSetAttribute(h16_gemm_nt, cudaFuncAttributeMaxDynamicSharedMemorySize, GEMM_SMEM);
        smem_set = 1;
    }

    // convert weights to fp16 (f1 also row-interleaved for fused GLU)
    {
        int n;
        n = 4 * DPROJ * DM / 4;      conv_copy_h<<<(n + 255) / 256, 256>>>(inw, winw, n);
        n = 4 * DM * DI / 4;         conv_copy_h<<<(n + 255) / 256, 256>>>(ow, wow, n);
        n = 4 * 2 * DINTER * DM / 4; conv_interleave_f1_h<<<(n + 255) / 256, 256>>>(f1w, wf1);
        n = 4 * DM * DINTER / 4;     conv_copy_h<<<(n + 255) / 256, 256>>>(f2w, wf2, n);
    }

    for (int i = 0; i < 4; i++) {
        int rev = i & 1;
        const float* xin = (i == 0) ? in_x : xb;
        const float* cwl = cw + (size_t)i * CONVD * 4;
        const float* cbl = cb + (size_t)i * CONVD;

        add_ln_kernel<<<ROWS, 128>>>(xin, resid, n1w + i * DM, n1b + i * DM, hh, (i == 0) ? 1 : 0, 1);

        {   // in_proj [8192 x 2096 x 512] -> zx fp16
            dim3 grid((DPROJ + 255) / 256, ROWS / 128);
            h16_gemm_nt<<<grid, 256, GEMM_SMEM>>>(ROWS, DPROJ, DM, hh, winw + (size_t)i * DPROJ * DM, zx, 2);
        }

        {   // chunked scan with fused conv
            dim3 gs(NC, NH, BATCH);
            chunk_state_kernel<<<gs, 256>>>(zx, cwl, cbl, dtb + i * NH, alog + i * NH, sloc, cdec, rev);
            chunk_scan_state<<<BATCH * NH, 256>>>(sloc, cdec, hinit);
            chunk_output_kernel<<<gs, 256>>>(zx, cwl, cbl, dtb + i * NH, alog + i * NH, hinit, Dp + i * NH, ybuf, rev);
        }

        gate_rms<<<ROWS, 256>>>(zx, ybuf, gw + i * DI, yh);

        {   // out_proj [8192 x 512 x 1024]
            dim3 grid(DM / 256, ROWS / 128);
            h16_gemm_nt<<<grid, 256, GEMM_SMEM>>>(ROWS, DM, DI, yh, wow + (size_t)i * DM * DI, tmp, 0);
        }

        add_ln_kernel<<<ROWS, 128>>>(tmp, resid, n2w + i * DM, n2b + i * DM, hh, 0, 1);

        {   // FFN f1 + fused GLU
            dim3 grid(DM / 256, ROWS / 128);
            h16_gemm_nt<<<grid, 256, GEMM_SMEM>>>(ROWS, DM, DM, hh, wf1 + (size_t)i * DM * DM, gluh, 1);
        }

        {   // FFN f2 [8192 x 512 x 256]
            dim3 grid(DM / 256, ROWS / 128);
            h16_gemm_nt<<<grid, 256, GEMM_SMEM>>>(ROWS, DM, DINTER, gluh, wf2 + (size_t)i * DM * DINTER, xb, 0);
        }
    }

    add_ln_kernel<<<ROWS, 128>>>(xb, resid, nfw, nfb, (float*)d_out, 0, 0);
}

// round 13
// speedup vs baseline: 1.0803x; 1.0803x over previous
#include <cuda_runtime.h>
#include <cuda_fp16.h>
#include <math.h>
#include <stdint.h>

#define BATCH 4
#define T 2048
#define DM 512
#define DI 1024
#define NH 16
#define HD 64
#define DS 16
#define CONVD 1056
#define DPROJ 2096
#define DINTER 256
#define ROWS (BATCH*T)

// chunked scan
#define CQ 64
#define NC (T/CQ)

// fp16 GEMM tiling: block 128(M) x 128(N), BK=64 halves, 3 stages, 2 CTAs/SM
#define BKH 64
#define LDA 72                      // halves per smem row (144 B)
#define A_ST_BYTES (128*144)
#define B_ST_BYTES (128*144)
#define ST_BYTES (A_ST_BYTES+B_ST_BYTES)   // 36864
#define STG 3
#define GEMM_SMEM (STG*ST_BYTES)    // 110592

// ---------------- scratch ----------------
__device__ float g_resid[ROWS*DM];
__device__ __half g_hh[ROWS*DM];          // LN output (fp16, GEMM A)
__device__ __half g_zx[ROWS*DPROJ];       // in_proj output (fp16)
__device__ float g_xbc[ROWS*CONVD];
__device__ float g_y[ROWS*DI];
__device__ __half g_yh[ROWS*DI];
__device__ float g_tmp[ROWS*DM];
__device__ __half g_gluh[ROWS*DINTER];
__device__ float g_x[ROWS*DM];
__device__ float g_sloc[BATCH*NH*NC*HD*DS];
__device__ float g_hinit[BATCH*NH*NC*HD*DS];
__device__ float g_cdecay[BATCH*NH*NC];
// fp16 weights
__device__ __half g_winw[4*DPROJ*DM];
__device__ __half g_wow[4*DM*DI];
__device__ __half g_wf1[4*2*DINTER*DM];
__device__ __half g_wf2[4*DM*DINTER];

// ---------------- weight conversion ----------------
__global__ void conv_copy_h(const float* __restrict__ src, __half* __restrict__ dst, int n4) {
    int i = blockIdx.x * blockDim.x + threadIdx.x;
    if (i >= n4) return;
    float4 v = ((const float4*)src)[i];
    ((__half2*)dst)[2 * i]     = __floats2half2_rn(v.x, v.y);
    ((__half2*)dst)[2 * i + 1] = __floats2half2_rn(v.z, v.w);
}

__global__ void conv_interleave_f1_h(const float* __restrict__ src, __half* __restrict__ dst) {
    int i = blockIdx.x * blockDim.x + threadIdx.x;
    int total4 = 4 * 512 * 512 / 4;
    if (i >= total4) return;
    int k4 = i & 127;
    int row = (i >> 7) & 511;
    int l = i >> 16;
    float4 v = ((const float4*)src)[i];
    int drow = (row < 256) ? (2 * row) : (2 * (row - 256) + 1);
    size_t o = (((size_t)l * 512 + drow) * 512 + k4 * 4);
    ((__half2*)(dst + o))[0] = __floats2half2_rn(v.x, v.y);
    ((__half2*)(dst + o))[1] = __floats2half2_rn(v.z, v.w);
}

// ---------------- residual add + LayerNorm ----------------
__global__ void add_ln_kernel(const float* __restrict__ xin, float* __restrict__ resid,
                              const float* __restrict__ w, const float* __restrict__ bch,
                              void* __restrict__ out, int first, int to_half) {
    int row = blockIdx.x;
    const float* xr = xin + (size_t)row * DM;
    float* rr = resid + (size_t)row * DM;
    int tid = threadIdx.x;
    float v[4]; float s = 0.f, s2 = 0.f;
#pragma unroll
    for (int j = 0; j < 4; j++) {
        int c = tid + j * 128;
        float val = xr[c];
        if (!first) val += rr[c];
        v[j] = val; s += val; s2 += val * val;
    }
#pragma unroll
    for (int o = 16; o > 0; o >>= 1) {
        s  += __shfl_xor_sync(0xffffffffu, s, o);
        s2 += __shfl_xor_sync(0xffffffffu, s2, o);
    }
    __shared__ float rs[4], rs2[4];
    int wid = tid >> 5;
    if ((tid & 31) == 0) { rs[wid] = s; rs2[wid] = s2; }
    __syncthreads();
    float tot  = rs[0] + rs[1] + rs[2] + rs[3];
    float tot2 = rs2[0] + rs2[1] + rs2[2] + rs2[3];
    float mu = tot * (1.f / DM);
    float var = tot2 * (1.f / DM) - mu * mu;
    float inv = rsqrtf(var + 1e-5f);
#pragma unroll
    for (int j = 0; j < 4; j++) {
        int c = tid + j * 128;
        float val = v[j];
        rr[c] = val;
        float o2 = (val - mu) * inv * w[c] + bch[c];
        if (to_half) ((__half*)out)[(size_t)row * DM + c] = __float2half_rn(o2);
        else         ((float*)out)[(size_t)row * DM + c] = o2;
    }
}

// ---------------- fp16 tensor-core NT GEMM (128x128, 3-stage, 2 CTA/SM) ----------------
#define MMA_F16(d, a, b) \
    asm volatile("mma.sync.aligned.m16n8k16.row.col.f32.f16.f16.f32 " \
                 "{%0,%1,%2,%3},{%4,%5,%6,%7},{%8,%9},{%0,%1,%2,%3};" \
                 : "+f"(d[0]), "+f"(d[1]), "+f"(d[2]), "+f"(d[3]) \
                 : "r"(a[0]), "r"(a[1]), "r"(a[2]), "r"(a[3]), "r"(b[0]), "r"(b[1]))

#define LDSM_X4(R, addr) \
    asm volatile("ldmatrix.sync.aligned.m8n8.x4.shared.b16 {%0,%1,%2,%3}, [%4];" \
                 : "=r"((R)[0]), "=r"((R)[1]), "=r"((R)[2]), "=r"((R)[3]) : "r"(addr))

__device__ __forceinline__ void gemm_load_stage(
    const __half* __restrict__ A, const __half* __restrict__ Bw,
    int K, int N, int bm, int bn, int it, int s, int tid, uint32_t sbase)
{
    int k0 = it * BKH;
    uint32_t stA = sbase + (uint32_t)s * ST_BYTES;
    uint32_t stB = stA + A_ST_BYTES;
#pragma unroll
    for (int i = 0; i < 4; i++) {
        int idx = i * 256 + tid;
        int row = idx >> 3, c = idx & 7;
        uint32_t dst = stA + (uint32_t)row * 144u + (uint32_t)(c << 4);
        const __half* gp = A + (size_t)(bm + row) * K + k0 + c * 8;
        asm volatile("cp.async.cg.shared.global [%0], [%1], 16;" :: "r"(dst), "l"(gp));
    }
#pragma unroll
    for (int i = 0; i < 4; i++) {
        int idx = i * 256 + tid;
        int row = idx >> 3, c = idx & 7;
        int rb = bn + row;
        int valid = (rb < N);
        uint32_t dst = stB + (uint32_t)row * 144u + (uint32_t)(c << 4);
        const __half* gp = Bw + (size_t)(valid ? rb : 0) * K + k0 + c * 8;
        int ssz = valid ? 16 : 0;
        asm volatile("cp.async.cg.shared.global [%0], [%1], 16, %2;" :: "r"(dst), "l"(gp), "r"(ssz));
    }
    asm volatile("cp.async.commit_group;" ::: "memory");
}

// out_mode: 0 = fp32 C, 1 = fused GLU (fp16, N/2 cols), 2 = fp16 C
__global__ void __launch_bounds__(256, 2) h16_gemm_nt(int M, int N, int K,
                                                      const __half* __restrict__ A,
                                                      const __half* __restrict__ Bw,
                                                      void* __restrict__ Cv, int out_mode) {
    extern __shared__ char smem[];
    uint32_t sbase = (uint32_t)__cvta_generic_to_shared(smem);
    int bm = blockIdx.y * 128, bn = blockIdx.x * 128;
    int tid = threadIdx.x;
    int wid = tid >> 5, lane = tid & 31;
    int wm = (wid & 1) * 64;        // 2 warps along M
    int wn = (wid >> 1) * 32;       // 4 warps along N, warp tile 64x32
    int g = lane >> 2, tig = lane & 3;

    int arow = lane & 15;
    int acol = (lane >> 4) << 3;
    int brow = ((lane >> 4) << 3) + (lane & 7);
    int bcol = ((lane >> 3) & 1) << 3;
    uint32_t aoff = ((uint32_t)((wm + arow) * LDA + acol)) * 2u;
    uint32_t boff = ((uint32_t)((wn + brow) * LDA + bcol)) * 2u + A_ST_BYTES;

    float acc[4][4][4];
#pragma unroll
    for (int i = 0; i < 4; i++)
#pragma unroll
        for (int j = 0; j < 4; j++)
#pragma unroll
            for (int k = 0; k < 4; k++) acc[i][j][k] = 0.f;

    int NIT = K / BKH;
#pragma unroll
    for (int p = 0; p < STG - 1; p++)
        if (p < NIT) gemm_load_stage(A, Bw, K, N, bm, bn, p, p, tid, sbase);

    for (int it = 0; it < NIT; ++it) {
        int pend = NIT - it - 1; if (pend > STG - 2) pend = STG - 2;
        if (pend == 1) asm volatile("cp.async.wait_group 1;" ::: "memory");
        else           asm volatile("cp.async.wait_group 0;" ::: "memory");
        __syncthreads();

        int ld = it + STG - 1;
        if (ld < NIT) gemm_load_stage(A, Bw, K, N, bm, bn, ld, ld % STG, tid, sbase);

        int s = it % STG;
        uint32_t Ab = sbase + (uint32_t)s * ST_BYTES + aoff;
        uint32_t Bb = sbase + (uint32_t)s * ST_BYTES + boff;
#pragma unroll
        for (int ks = 0; ks < 4; ks++) {
            uint32_t kbyte = (uint32_t)(ks * 16 * 2);
            uint32_t a[4][4], b[2][4];
#pragma unroll
            for (int mt = 0; mt < 4; mt++)
                LDSM_X4(a[mt], Ab + (uint32_t)(mt * 16 * LDA) * 2u + kbyte);
#pragma unroll
            for (int np = 0; np < 2; np++)
                LDSM_X4(b[np], Bb + (uint32_t)(np * 16 * LDA) * 2u + kbyte);
#pragma unroll
            for (int mt = 0; mt < 4; mt++)
#pragma unroll
                for (int np = 0; np < 2; np++) {
                    MMA_F16(acc[mt][2 * np], a[mt], b[np]);
                    uint32_t bhi[2] = { b[np][2], b[np][3] };
                    MMA_F16(acc[mt][2 * np + 1], a[mt], bhi);
                }
        }
    }

    if (out_mode == 0) {
        float* C = (float*)Cv;
#pragma unroll
        for (int mt = 0; mt < 4; mt++) {
            int r0 = bm + wm + mt * 16 + g;
#pragma unroll
            for (int nt = 0; nt < 4; nt++) {
                int c0 = bn + wn + nt * 8 + tig * 2;
                if (c0 < N) {
                    *(float2*)&C[(size_t)r0 * N + c0] = make_float2(acc[mt][nt][0], acc[mt][nt][1]);
                    *(float2*)&C[(size_t)(r0 + 8) * N + c0] = make_float2(acc[mt][nt][2], acc[mt][nt][3]);
                }
            }
        }
    } else if (out_mode == 2) {
        __half* C = (__half*)Cv;
#pragma unroll
        for (int mt = 0; mt < 4; mt++) {
            int r0 = bm + wm + mt * 16 + g;
#pragma unroll
            for (int nt = 0; nt < 4; nt++) {
                int c0 = bn + wn + nt * 8 + tig * 2;
                if (c0 < N) {
                    *(__half2*)&C[(size_t)r0 * N + c0] = __floats2half2_rn(acc[mt][nt][0], acc[mt][nt][1]);
                    *(__half2*)&C[(size_t)(r0 + 8) * N + c0] = __floats2half2_rn(acc[mt][nt][2], acc[mt][nt][3]);
                }
            }
        }
    } else {
        __half* C = (__half*)Cv;
        int No = N >> 1;
#pragma unroll
        for (int mt = 0; mt < 4; mt++) {
            int r0 = bm + wm + mt * 16 + g;
#pragma unroll
            for (int nt = 0; nt < 4; nt++) {
                int c0 = bn + wn + nt * 8 + tig * 2;   // even
                if (c0 < N) {
                    float a0 = acc[mt][nt][0], g0 = acc[mt][nt][1];
                    float a1 = acc[mt][nt][2], g1 = acc[mt][nt][3];
                    C[(size_t)r0 * No + (c0 >> 1)] = __float2half_rn(a0 * g0 / (1.f + expf(-g0)));
                    C[(size_t)(r0 + 8) * No + (c0 >> 1)] = __float2half_rn(a1 * g1 / (1.f + expf(-g1)));
                }
            }
        }
    }
}

// ---------------- depthwise causal conv (fp16 in, fp32 out): 4 t-steps/thread ----------------
__global__ void conv_silu(const __half* __restrict__ zx, const float* __restrict__ cw,
                          const float* __restrict__ cb, float* __restrict__ out, int rev) {
    int idx = blockIdx.x * blockDim.x + threadIdx.x;
    if (idx >= (ROWS / 4) * CONVD) return;
    int c = idx % CONVD; int tt = idx / CONVD;
    int b = tt / (T / 4); int t0 = (tt % (T / 4)) * 4;
    const float* w = cw + c * 4;
    const __half* col = zx + (size_t)b * T * DPROJ + DI + c;
    float bias = cb[c];
    float win[7];
    if (!rev) {
#pragma unroll
        for (int j = 0; j < 7; j++) {
            int t = t0 - 3 + j;
            win[j] = (t >= 0) ? __half2float(col[(size_t)t * DPROJ]) : 0.f;
        }
#pragma unroll
        for (int i = 0; i < 4; i++) {
            float acc = bias;
#pragma unroll
            for (int k = 0; k < 4; k++) acc += w[k] * win[i + k];
            out[((size_t)b * T + t0 + i) * CONVD + c] = acc / (1.f + expf(-acc));
        }
    } else {
#pragma unroll
        for (int j = 0; j < 7; j++) {
            int t = t0 + j;
            win[j] = (t < T) ? __half2float(col[(size_t)t * DPROJ]) : 0.f;
        }
#pragma unroll
        for (int i = 0; i < 4; i++) {
            float acc = bias;
#pragma unroll
            for (int k = 0; k < 4; k++) acc += w[k] * win[i + 3 - k];
            out[((size_t)b * T + t0 + i) * CONVD + c] = acc / (1.f + expf(-acc));
        }
    }
}

// ---------------- chunked SSD scan (dt computed inline from zx) ----------------
__global__ void __launch_bounds__(256) chunk_state_kernel(
    const float* __restrict__ xbc, const __half* __restrict__ zx,
    const float* __restrict__ dtb, const float* __restrict__ alog,
    float* __restrict__ sloc, float* __restrict__ cdecay, int rev)
{
    int c = blockIdx.x, head = blockIdx.y, b = blockIdx.z;
    int tid = threadIdx.x;
    __shared__ float Xs[CQ][HD + 4];
    __shared__ float Bs[CQ][DS + 1];
    __shared__ float Ls[CQ];
    __shared__ float wdt[CQ];
    size_t tbase = (size_t)b * T;
    float A = -expf(alog[head]);

    for (int i = tid; i < CQ * HD; i += 256) {
        int j = i >> 6, p = i & 63;
        int s = c * CQ + j;
        int t = rev ? (T - 1 - s) : s;
        Xs[j][p] = xbc[(tbase + t) * CONVD + head * HD + p];
    }
    for (int i = tid; i < CQ * DS; i += 256) {
        int j = i >> 4, n = i & 15;
        int s = c * CQ + j;
        int t = rev ? (T - 1 - s) : s;
        Bs[j][n] = xbc[(tbase + t) * CONVD + DI + n];
    }
    if (tid < CQ) {
        int s = c * CQ + tid;
        int t = rev ? (T - 1 - s) : s;
        float raw = __half2float(zx[(tbase + t) * DPROJ + (DI + CONVD) + head]) + dtb[head];
        float d = (raw > 20.f) ? raw : log1pf(expf(raw));
        wdt[tid] = d;
        Ls[tid] = d * A;
    }
    __syncthreads();
    for (int off = 1; off < CQ; off <<= 1) {
        float v = 0.f;
        if (tid < CQ) v = Ls[tid] + ((tid >= off) ? Ls[tid - off] : 0.f);
        __syncthreads();
        if (tid < CQ) Ls[tid] = v;
        __syncthreads();
    }
    float Lend = Ls[CQ - 1];

    int p = tid >> 2, ng = (tid & 3) << 2;
    float acc0 = 0.f, acc1 = 0.f, acc2 = 0.f, acc3 = 0.f;
    for (int j = 0; j < CQ; j++) {
        float w = expf(Lend - Ls[j]) * wdt[j];
        float xv = w * Xs[j][p];
        acc0 += xv * Bs[j][ng + 0];
        acc1 += xv * Bs[j][ng + 1];
        acc2 += xv * Bs[j][ng + 2];
        acc3 += xv * Bs[j][ng + 3];
    }
    size_t o = ((((size_t)b * NH + head) * NC + c) * HD + p) * DS + ng;
    sloc[o + 0] = acc0; sloc[o + 1] = acc1; sloc[o + 2] = acc2; sloc[o + 3] = acc3;
    if (tid == 0) cdecay[((size_t)b * NH + head) * NC + c] = expf(Lend);
}

__global__ void __launch_bounds__(256) chunk_scan_state(
    const float* __restrict__ sloc, const float* __restrict__ cdecay,
    float* __restrict__ hinit)
{
    int bh = blockIdx.x;
    int tid = threadIdx.x;
    float h0 = 0.f, h1 = 0.f, h2 = 0.f, h3 = 0.f;
    for (int c = 0; c < NC; c++) {
        size_t base = ((size_t)bh * NC + c) * (HD * DS);
        float d = cdecay[(size_t)bh * NC + c];
        size_t i0 = base + tid, i1 = base + tid + 256, i2 = base + tid + 512, i3 = base + tid + 768;
        hinit[i0] = h0; hinit[i1] = h1; hinit[i2] = h2; hinit[i3] = h3;
        h0 = d * h0 + sloc[i0];
        h1 = d * h1 + sloc[i1];
        h2 = d * h2 + sloc[i2];
        h3 = d * h3 + sloc[i3];
    }
}

__global__ void __launch_bounds__(256) chunk_output_kernel(
    const float* __restrict__ xbc, const __half* __restrict__ zx,
    const float* __restrict__ dtb, const float* __restrict__ alog,
    const float* __restrict__ hinit, const float* __restrict__ Dp,
    float* __restrict__ y, int rev)
{
    int c = blockIdx.x, head = blockIdx.y, b = blockIdx.z;
    int tid = threadIdx.x;
    __shared__ float Xs[CQ][HD + 4];
    __shared__ float Bs[CQ][DS + 1];
    __shared__ float Cs[CQ][DS + 1];
    __shared__ float h0s[HD][DS + 1];
    __shared__ float Ls[CQ];
    __shared__ float wdt[CQ];
    __shared__ float Ss[CQ][CQ + 1];
    size_t tbase = (size_t)b * T;
    float A = -expf(alog[head]);

    for (int i = tid; i < CQ * HD; i += 256) {
        int j = i >> 6, p = i & 63;
        int s = c * CQ + j;
        int t = rev ? (T - 1 - s) : s;
        Xs[j][p] = xbc[(tbase + t) * CONVD + head * HD + p];
    }
    for (int i = tid; i < CQ * DS; i += 256) {
        int j = i >> 4, n = i & 15;
        int s = c * CQ + j;
        int t = rev ? (T - 1 - s) : s;
        size_t row = (tbase + t) * CONVD + DI;
        Bs[j][n] = xbc[row + n];
        Cs[j][n] = xbc[row + DS + n];
    }
    {
        size_t hb = ((((size_t)b * NH + head) * NC + c) * HD) * DS;
        for (int i = tid; i < HD * DS; i += 256) {
            int p = i >> 4, n = i & 15;
            h0s[p][n] = hinit[hb + i];
        }
    }
    if (tid < CQ) {
        int s = c * CQ + tid;
        int t = rev ? (T - 1 - s) : s;
        float raw = __half2float(zx[(tbase + t) * DPROJ + (DI + CONVD) + head]) + dtb[head];
        float d = (raw > 20.f) ? raw : log1pf(expf(raw));
        wdt[tid] = d;
        Ls[tid] = d * A;
    }
    __syncthreads();
    for (int off = 1; off < CQ; off <<= 1) {
        float v = 0.f;
        if (tid < CQ) v = Ls[tid] + ((tid >= off) ? Ls[tid - off] : 0.f);
        __syncthreads();
        if (tid < CQ) Ls[tid] = v;
        __syncthreads();
    }

    int t = tid >> 2;
    int quad = tid & 3;
    float Ct[DS];
#pragma unroll
    for (int n = 0; n < DS; n++) Ct[n] = Cs[t][n];
    float Lt = Ls[t];

    int jb = quad * 16;
#pragma unroll
    for (int q = 0; q < 16; q++) {
        int j = jb + q;
        float sv = 0.f;
        if (j <= t) {
            float dot = 0.f;
#pragma unroll
            for (int n = 0; n < DS; n++) dot += Ct[n] * Bs[j][n];
            sv = expf(Lt - Ls[j]) * wdt[j] * dot;
        }
        Ss[t][j] = sv;
    }
    __syncthreads();

    int pb = quad * 16;
    float acc[16];
#pragma unroll
    for (int k = 0; k < 16; k++) acc[k] = 0.f;
    for (int j = 0; j <= t; j++) {
        float sv = Ss[t][j];
#pragma unroll
        for (int k4 = 0; k4 < 4; k4++) {
            float4 xv = *(const float4*)&Xs[j][pb + k4 * 4];
            acc[k4 * 4 + 0] += sv * xv.x;
            acc[k4 * 4 + 1] += sv * xv.y;
            acc[k4 * 4 + 2] += sv * xv.z;
            acc[k4 * 4 + 3] += sv * xv.w;
        }
    }
    float et = expf(Lt);
    float Dv = Dp[head];
#pragma unroll
    for (int k = 0; k < 16; k++) {
        int p = pb + k;
        float dot = 0.f;
#pragma unroll
        for (int n = 0; n < DS; n++) dot += Ct[n] * h0s[p][n];
        acc[k] += et * dot + Dv * Xs[t][p];
    }
    int s_idx = c * CQ + t;
    int trow = rev ? (T - 1 - s_idx) : s_idx;
    float* yr = y + (tbase + trow) * DI + head * HD + pb;
#pragma unroll
    for (int k4 = 0; k4 < 4; k4++) {
        *(float4*)(yr + k4 * 4) = make_float4(acc[k4 * 4 + 0], acc[k4 * 4 + 1], acc[k4 * 4 + 2], acc[k4 * 4 + 3]);
    }
}

// ---------------- y = y * silu(z); RMSNorm(y) * gw -> fp16 ----------------
__global__ void gate_rms(const __half* __restrict__ zx, const float* __restrict__ y,
                         const float* __restrict__ gw, __half* __restrict__ yh) {
    int row = blockIdx.x;
    const __half* z = zx + (size_t)row * DPROJ;
    const float* yr = y + (size_t)row * DI;
    __half* yo = yh + (size_t)row * DI;
    int tid = threadIdx.x;
    float v[4]; float s2 = 0.f;
#pragma unroll
    for (int j = 0; j < 4; j++) {
        int c = tid + j * 256;
        float zz = __half2float(z[c]);
        float val = yr[c] * (zz / (1.f + expf(-zz)));
        v[j] = val; s2 += val * val;
    }
#pragma unroll
    for (int o = 16; o > 0; o >>= 1) s2 += __shfl_xor_sync(0xffffffffu, s2, o);
    __shared__ float rs[8];
    int wid = tid >> 5;
    if ((tid & 31) == 0) rs[wid] = s2;
    __syncthreads();
    float tot = 0.f;
#pragma unroll
    for (int i = 0; i < 8; i++) tot += rs[i];
    float inv = rsqrtf(tot * (1.f / DI) + 1e-5f);
#pragma unroll
    for (int j = 0; j < 4; j++) {
        int c = tid + j * 256;
        yo[c] = __float2half_rn(v[j] * inv * gw[c]);
    }
}

// ---------------- host ----------------
static void* sym_addr_v(const void* sym) {
    void* p = nullptr;
    cudaGetSymbolAddress(&p, sym);
    return p;
}

extern "C" void kernel_launch(void* const* d_in, const int* in_sizes, int n_in,
                              void* d_out, int out_size) {
    const float* in_x   = (const float*)d_in[0];
    const float* n1w    = (const float*)d_in[1];
    const float* n1b    = (const float*)d_in[2];
    const float* inw    = (const float*)d_in[3];
    const float* cw     = (const float*)d_in[4];
    const float* cb     = (const float*)d_in[5];
    const float* dtb    = (const float*)d_in[6];
    const float* alog   = (const float*)d_in[7];
    const float* Dp     = (const float*)d_in[8];
    const float* gw     = (const float*)d_in[9];
    const float* ow     = (const float*)d_in[10];
    const float* n2w    = (const float*)d_in[11];
    const float* n2b    = (const float*)d_in[12];
    const float* f1w    = (const float*)d_in[13];
    const float* f2w    = (const float*)d_in[14];
    const float* nfw    = (const float*)d_in[15];
    const float* nfb    = (const float*)d_in[16];

    float*  resid = (float*) sym_addr_v(g_resid);
    __half* hh    = (__half*)sym_addr_v(g_hh);
    __half* zx    = (__half*)sym_addr_v(g_zx);
    float*  xbc   = (float*) sym_addr_v(g_xbc);
    float*  ybuf  = (float*) sym_addr_v(g_y);
    __half* yh    = (__half*)sym_addr_v(g_yh);
    float*  tmp   = (float*) sym_addr_v(g_tmp);
    __half* gluh  = (__half*)sym_addr_v(g_gluh);
    float*  xb    = (float*) sym_addr_v(g_x);
    float*  sloc  = (float*) sym_addr_v(g_sloc);
    float*  hinit = (float*) sym_addr_v(g_hinit);
    float*  cdec  = (float*) sym_addr_v(g_cdecay);
    __half* winw  = (__half*)sym_addr_v(g_winw);
    __half* wow   = (__half*)sym_addr_v(g_wow);
    __half* wf1   = (__half*)sym_addr_v(g_wf1);
    __half* wf2   = (__half*)sym_addr_v(g_wf2);

    static int smem_set = 0;
    if (!smem_set) {
        cudaFuncSetAttribute(h16_gemm_nt, cudaFuncAttributeMaxDynamicSharedMemorySize, GEMM_SMEM);
        smem_set = 1;
    }

    // convert weights to fp16 (f1 also row-interleaved for fused GLU)
    {
        int n;
        n = 4 * DPROJ * DM / 4;      conv_copy_h<<<(n + 255) / 256, 256>>>(inw, winw, n);
        n = 4 * DM * DI / 4;         conv_copy_h<<<(n + 255) / 256, 256>>>(ow, wow, n);
        n = 4 * 2 * DINTER * DM / 4; conv_interleave_f1_h<<<(n + 255) / 256, 256>>>(f1w, wf1);
        n = 4 * DM * DINTER / 4;     conv_copy_h<<<(n + 255) / 256, 256>>>(f2w, wf2, n);
    }

    for (int i = 0; i < 4; i++) {
        int rev = i & 1;
        const float* xin = (i == 0) ? in_x : xb;

        add_ln_kernel<<<ROWS, 128>>>(xin, resid, n1w + i * DM, n1b + i * DM, hh, (i == 0) ? 1 : 0, 1);

        {   // in_proj [8192 x 2096 x 512] -> zx fp16
            dim3 grid((DPROJ + 127) / 128, ROWS / 128);
            h16_gemm_nt<<<grid, 256, GEMM_SMEM>>>(ROWS, DPROJ, DM, hh, winw + (size_t)i * DPROJ * DM, zx, 2);
        }

        conv_silu<<<((ROWS / 4) * CONVD + 255) / 256, 256>>>(zx, cw + (size_t)i * CONVD * 4, cb + i * CONVD, xbc, rev);

        {
            dim3 gs(NC, NH, BATCH);
            chunk_state_kernel<<<gs, 256>>>(xbc, zx, dtb + i * NH, alog + i * NH, sloc, cdec, rev);
            chunk_scan_state<<<BATCH * NH, 256>>>(sloc, cdec, hinit);
            chunk_output_kernel<<<gs, 256>>>(xbc, zx, dtb + i * NH, alog + i * NH, hinit, Dp + i * NH, ybuf, rev);
        }

        gate_rms<<<ROWS, 256>>>(zx, ybuf, gw + i * DI, yh);

        {   // out_proj [8192 x 512 x 1024]
            dim3 grid(DM / 128, ROWS / 128);
            h16_gemm_nt<<<grid, 256, GEMM_SMEM>>>(ROWS, DM, DI, yh, wow + (size_t)i * DM * DI, tmp, 0);
        }

        add_ln_kernel<<<ROWS, 128>>>(tmp, resid, n2w + i * DM, n2b + i * DM, hh, 0, 1);

        {   // FFN f1 + fused GLU
            dim3 grid(DM / 128, ROWS / 128);
            h16_gemm_nt<<<grid, 256, GEMM_SMEM>>>(ROWS, DM, DM, hh, wf1 + (size_t)i * DM * DM, gluh, 1);
        }

        {   // FFN f2 [8192 x 512 x 256]
            dim3 grid(DM / 128, ROWS / 128);
            h16_gemm_nt<<<grid, 256, GEMM_SMEM>>>(ROWS, DM, DINTER, gluh, wf2 + (size_t)i * DM * DINTER, xb, 0);
        }
    }

    add_ln_kernel<<<ROWS, 128>>>(xb, resid, nfw, nfb, (float*)d_out, 0, 0);
}

// round 15
// speedup vs baseline: 1.1727x; 1.0856x over previous
#include <cuda_runtime.h>
#include <cuda_fp16.h>
#include <math.h>
#include <stdint.h>

#define BATCH 4
#define T 2048
#define DM 512
#define DI 1024
#define NH 16
#define HD 64
#define DS 16
#define CONVD 1056
#define DPROJ 2096
#define DINTER 256
#define ROWS (BATCH*T)

// chunked scan
#define CQ 64
#define NC (T/CQ)

// fp16 GEMM tiling: block 128(M) x 128(N), BK=64 halves, 3 stages, 2 CTAs/SM
#define BKH 64
#define LDA 72
#define A_ST_BYTES (128*144)
#define B_ST_BYTES (128*144)
#define ST_BYTES (A_ST_BYTES+B_ST_BYTES)
#define STG 3
#define GEMM_SMEM (STG*ST_BYTES)    // 110592

// ---------------- scratch ----------------
__device__ float g_resid[ROWS*DM];
__device__ __half g_hh[ROWS*DM];
__device__ __half g_zx[ROWS*DPROJ];
__device__ float g_xbc[ROWS*CONVD];
__device__ float g_y[ROWS*DI];
__device__ __half g_yh[ROWS*DI];
__device__ float g_tmp[ROWS*DM];
__device__ __half g_gluh[ROWS*DINTER];
__device__ float g_x[ROWS*DM];
__device__ float g_sloc[BATCH*NH*NC*HD*DS];
__device__ float g_hinit[BATCH*NH*NC*HD*DS];
__device__ float g_cdecay[BATCH*NH*NC];
// fp16 weights
__device__ __half g_winw[4*DPROJ*DM];
__device__ __half g_wow[4*DM*DI];
__device__ __half g_wf1[4*2*DINTER*DM];
__device__ __half g_wf2[4*DM*DINTER];

// ---------------- fused weight conversion (all four tensors, one launch) ----------------
// sizes (float4 units): inw 1073152, ow 524288, f1 262144 (interleaved), f2 131072
#define N4_INW (4*DPROJ*DM/4)
#define N4_OW  (4*DM*DI/4)
#define N4_F1  (4*2*DINTER*DM/4)
#define N4_F2  (4*DM*DINTER/4)
#define N4_ALL (N4_INW+N4_OW+N4_F1+N4_F2)

__global__ void conv_all_weights(const float* __restrict__ inw, const float* __restrict__ ow,
                                 const float* __restrict__ f1w, const float* __restrict__ f2w,
                                 __half* __restrict__ winw, __half* __restrict__ wow,
                                 __half* __restrict__ wf1, __half* __restrict__ wf2) {
    int i = blockIdx.x * blockDim.x + threadIdx.x;
    if (i >= N4_ALL) return;
    const float* src; __half* dst; int li;
    if (i < N4_INW) { src = inw; dst = winw; li = i; }
    else if (i < N4_INW + N4_OW) { src = ow; dst = wow; li = i - N4_INW; }
    else if (i < N4_INW + N4_OW + N4_F1) {
        // f1: round + row-interleave
        int j = i - N4_INW - N4_OW;
        float4 v = ((const float4*)f1w)[j];
        int k4 = j & 127;
        int row = (j >> 7) & 511;
        int l = j >> 16;
        int drow = (row < 256) ? (2 * row) : (2 * (row - 256) + 1);
        size_t o = (((size_t)l * 512 + drow) * 512 + k4 * 4);
        ((__half2*)(wf1 + o))[0] = __floats2half2_rn(v.x, v.y);
        ((__half2*)(wf1 + o))[1] = __floats2half2_rn(v.z, v.w);
        return;
    }
    else { src = f2w; dst = wf2; li = i - N4_INW - N4_OW - N4_F1; }
    float4 v = ((const float4*)src)[li];
    ((__half2*)dst)[2 * li]     = __floats2half2_rn(v.x, v.y);
    ((__half2*)dst)[2 * li + 1] = __floats2half2_rn(v.z, v.w);
}

// ---------------- residual add + LayerNorm (2 rows/block, float4) ----------------
__global__ void add_ln_kernel(const float* __restrict__ xin, float* __restrict__ resid,
                              const float* __restrict__ w, const float* __restrict__ bch,
                              void* __restrict__ out, int first, int to_half) {
    int row = blockIdx.x * 2 + (threadIdx.x >> 7);   // 256 threads = 2 half-blocks
    int tid = threadIdx.x & 127;
    int half_id = threadIdx.x >> 7;
    const float* xr = xin + (size_t)row * DM;
    float* rr = resid + (size_t)row * DM;
    float4 v = ((const float4*)xr)[tid];
    if (!first) {
        float4 r = ((const float4*)rr)[tid];
        v.x += r.x; v.y += r.y; v.z += r.z; v.w += r.w;
    }
    float s = v.x + v.y + v.z + v.w;
    float s2 = v.x * v.x + v.y * v.y + v.z * v.z + v.w * v.w;
#pragma unroll
    for (int o = 16; o > 0; o >>= 1) {
        s  += __shfl_xor_sync(0xffffffffu, s, o);
        s2 += __shfl_xor_sync(0xffffffffu, s2, o);
    }
    __shared__ float rs[8], rs2[8];
    int wid = threadIdx.x >> 5;
    if ((threadIdx.x & 31) == 0) { rs[wid] = s; rs2[wid] = s2; }
    __syncthreads();
    int wb = half_id * 4;
    float tot  = rs[wb] + rs[wb + 1] + rs[wb + 2] + rs[wb + 3];
    float tot2 = rs2[wb] + rs2[wb + 1] + rs2[wb + 2] + rs2[wb + 3];
    float mu = tot * (1.f / DM);
    float var = tot2 * (1.f / DM) - mu * mu;
    float inv = rsqrtf(var + 1e-5f);
    ((float4*)rr)[tid] = v;
    float4 wv = ((const float4*)w)[tid];
    float4 bv = ((const float4*)bch)[tid];
    float o0 = (v.x - mu) * inv * wv.x + bv.x;
    float o1 = (v.y - mu) * inv * wv.y + bv.y;
    float o2 = (v.z - mu) * inv * wv.z + bv.z;
    float o3 = (v.w - mu) * inv * wv.w + bv.w;
    if (to_half) {
        __half2* op = (__half2*)((__half*)out + (size_t)row * DM);
        op[2 * tid]     = __floats2half2_rn(o0, o1);
        op[2 * tid + 1] = __floats2half2_rn(o2, o3);
    } else {
        ((float4*)((float*)out + (size_t)row * DM))[tid] = make_float4(o0, o1, o2, o3);
    }
}

// ---------------- fp16 tensor-core NT GEMM (128x128, 3-stage, 2 CTA/SM) ----------------
#define MMA_F16(d, a, b) \
    asm volatile("mma.sync.aligned.m16n8k16.row.col.f32.f16.f16.f32 " \
                 "{%0,%1,%2,%3},{%4,%5,%6,%7},{%8,%9},{%0,%1,%2,%3};" \
                 : "+f"(d[0]), "+f"(d[1]), "+f"(d[2]), "+f"(d[3]) \
                 : "r"(a[0]), "r"(a[1]), "r"(a[2]), "r"(a[3]), "r"(b[0]), "r"(b[1]))

#define LDSM_X4(R, addr) \
    asm volatile("ldmatrix.sync.aligned.m8n8.x4.shared.b16 {%0,%1,%2,%3}, [%4];" \
                 : "=r"((R)[0]), "=r"((R)[1]), "=r"((R)[2]), "=r"((R)[3]) : "r"(addr))

__device__ __forceinline__ void gemm_load_stage(
    const __half* __restrict__ A, const __half* __restrict__ Bw,
    int K, int N, int bm, int bn, int it, int s, int tid, uint32_t sbase)
{
    int k0 = it * BKH;
    uint32_t stA = sbase + (uint32_t)s * ST_BYTES;
    uint32_t stB = stA + A_ST_BYTES;
#pragma unroll
    for (int i = 0; i < 4; i++) {
        int idx = i * 256 + tid;
        int row = idx >> 3, c = idx & 7;
        uint32_t dst = stA + (uint32_t)row * 144u + (uint32_t)(c << 4);
        const __half* gp = A + (size_t)(bm + row) * K + k0 + c * 8;
        asm volatile("cp.async.cg.shared.global [%0], [%1], 16;" :: "r"(dst), "l"(gp));
    }
#pragma unroll
    for (int i = 0; i < 4; i++) {
        int idx = i * 256 + tid;
        int row = idx >> 3, c = idx & 7;
        int rb = bn + row;
        int valid = (rb < N);
        uint32_t dst = stB + (uint32_t)row * 144u + (uint32_t)(c << 4);
        const __half* gp = Bw + (size_t)(valid ? rb : 0) * K + k0 + c * 8;
        int ssz = valid ? 16 : 0;
        asm volatile("cp.async.cg.shared.global [%0], [%1], 16, %2;" :: "r"(dst), "l"(gp), "r"(ssz));
    }
    asm volatile("cp.async.commit_group;" ::: "memory");
}

// out_mode: 0 = fp32 C, 1 = fused GLU (fp16, N/2 cols), 2 = fp16 C
__global__ void __launch_bounds__(256, 2) h16_gemm_nt(int M, int N, int K,
                                                      const __half* __restrict__ A,
                                                      const __half* __restrict__ Bw,
                                                      void* __restrict__ Cv, int out_mode) {
    extern __shared__ char smem[];
    uint32_t sbase = (uint32_t)__cvta_generic_to_shared(smem);
    int bm = blockIdx.y * 128, bn = blockIdx.x * 128;
    int tid = threadIdx.x;
    int wid = tid >> 5, lane = tid & 31;
    int wm = (wid & 1) * 64;
    int wn = (wid >> 1) * 32;
    int g = lane >> 2, tig = lane & 3;

    int arow = lane & 15;
    int acol = (lane >> 4) << 3;
    int brow = ((lane >> 4) << 3) + (lane & 7);
    int bcol = ((lane >> 3) & 1) << 3;
    uint32_t aoff = ((uint32_t)((wm + arow) * LDA + acol)) * 2u;
    uint32_t boff = ((uint32_t)((wn + brow) * LDA + bcol)) * 2u + A_ST_BYTES;

    float acc[4][4][4];
#pragma unroll
    for (int i = 0; i < 4; i++)
#pragma unroll
        for (int j = 0; j < 4; j++)
#pragma unroll
            for (int k = 0; k < 4; k++) acc[i][j][k] = 0.f;

    int NIT = K / BKH;
#pragma unroll
    for (int p = 0; p < STG - 1; p++)
        if (p < NIT) gemm_load_stage(A, Bw, K, N, bm, bn, p, p, tid, sbase);

    for (int it = 0; it < NIT; ++it) {
        int pend = NIT - it - 1; if (pend > STG - 2) pend = STG - 2;
        if (pend == 1) asm volatile("cp.async.wait_group 1;" ::: "memory");
        else           asm volatile("cp.async.wait_group 0;" ::: "memory");
        __syncthreads();

        int ld = it + STG - 1;
        if (ld < NIT) gemm_load_stage(A, Bw, K, N, bm, bn, ld, ld % STG, tid, sbase);

        int s = it % STG;
        uint32_t Ab = sbase + (uint32_t)s * ST_BYTES + aoff;
        uint32_t Bb = sbase + (uint32_t)s * ST_BYTES + boff;
#pragma unroll
        for (int ks = 0; ks < 4; ks++) {
            uint32_t kbyte = (uint32_t)(ks * 16 * 2);
            uint32_t a[4][4], b[2][4];
#pragma unroll
            for (int mt = 0; mt < 4; mt++)
                LDSM_X4(a[mt], Ab + (uint32_t)(mt * 16 * LDA) * 2u + kbyte);
#pragma unroll
            for (int np = 0; np < 2; np++)
                LDSM_X4(b[np], Bb + (uint32_t)(np * 16 * LDA) * 2u + kbyte);
#pragma unroll
            for (int mt = 0; mt < 4; mt++)
#pragma unroll
                for (int np = 0; np < 2; np++) {
                    MMA_F16(acc[mt][2 * np], a[mt], b[np]);
                    uint32_t bhi[2] = { b[np][2], b[np][3] };
                    MMA_F16(acc[mt][2 * np + 1], a[mt], bhi);
                }
        }
    }

    if (out_mode == 0) {
        float* C = (float*)Cv;
#pragma unroll
        for (int mt = 0; mt < 4; mt++) {
            int r0 = bm + wm + mt * 16 + g;
#pragma unroll
            for (int nt = 0; nt < 4; nt++) {
                int c0 = bn + wn + nt * 8 + tig * 2;
                if (c0 < N) {
                    *(float2*)&C[(size_t)r0 * N + c0] = make_float2(acc[mt][nt][0], acc[mt][nt][1]);
                    *(float2*)&C[(size_t)(r0 + 8) * N + c0] = make_float2(acc[mt][nt][2], acc[mt][nt][3]);
                }
            }
        }
    } else if (out_mode == 2) {
        __half* C = (__half*)Cv;
#pragma unroll
        for (int mt = 0; mt < 4; mt++) {
            int r0 = bm + wm + mt * 16 + g;
#pragma unroll
            for (int nt = 0; nt < 4; nt++) {
                int c0 = bn + wn + nt * 8 + tig * 2;
                if (c0 < N) {
                    *(__half2*)&C[(size_t)r0 * N + c0] = __floats2half2_rn(acc[mt][nt][0], acc[mt][nt][1]);
                    *(__half2*)&C[(size_t)(r0 + 8) * N + c0] = __floats2half2_rn(acc[mt][nt][2], acc[mt][nt][3]);
                }
            }
        }
    } else {
        __half* C = (__half*)Cv;
        int No = N >> 1;
#pragma unroll
        for (int mt = 0; mt < 4; mt++) {
            int r0 = bm + wm + mt * 16 + g;
#pragma unroll
            for (int nt = 0; nt < 4; nt++) {
                int c0 = bn + wn + nt * 8 + tig * 2;
                if (c0 < N) {
                    float a0 = acc[mt][nt][0], g0 = acc[mt][nt][1];
                    float a1 = acc[mt][nt][2], g1 = acc[mt][nt][3];
                    C[(size_t)r0 * No + (c0 >> 1)] = __float2half_rn(a0 * g0 / (1.f + expf(-g0)));
                    C[(size_t)(r0 + 8) * No + (c0 >> 1)] = __float2half_rn(a1 * g1 / (1.f + expf(-g1)));
                }
            }
        }
    }
}

// ---------------- depthwise causal conv (fp16 in, fp32 out): 4 t-steps/thread ----------------
__global__ void conv_silu(const __half* __restrict__ zx, const float* __restrict__ cw,
                          const float* __restrict__ cb, float* __restrict__ out, int rev) {
    int idx = blockIdx.x * blockDim.x + threadIdx.x;
    if (idx >= (ROWS / 4) * CONVD) return;
    int c = idx % CONVD; int tt = idx / CONVD;
    int b = tt / (T / 4); int t0 = (tt % (T / 4)) * 4;
    const float* w = cw + c * 4;
    const __half* col = zx + (size_t)b * T * DPROJ + DI + c;
    float bias = cb[c];
    float win[7];
    if (!rev) {
#pragma unroll
        for (int j = 0; j < 7; j++) {
            int t = t0 - 3 + j;
            win[j] = (t >= 0) ? __half2float(col[(size_t)t * DPROJ]) : 0.f;
        }
#pragma unroll
        for (int i = 0; i < 4; i++) {
            float acc = bias;
#pragma unroll
            for (int k = 0; k < 4; k++) acc += w[k] * win[i + k];
            out[((size_t)b * T + t0 + i) * CONVD + c] = acc / (1.f + expf(-acc));
        }
    } else {
#pragma unroll
        for (int j = 0; j < 7; j++) {
            int t = t0 + j;
            win[j] = (t < T) ? __half2float(col[(size_t)t * DPROJ]) : 0.f;
        }
#pragma unroll
        for (int i = 0; i < 4; i++) {
            float acc = bias;
#pragma unroll
            for (int k = 0; k < 4; k++) acc += w[k] * win[i + 3 - k];
            out[((size_t)b * T + t0 + i) * CONVD + c] = acc / (1.f + expf(-acc));
        }
    }
}

// ---------------- chunked SSD scan (dt computed inline from zx) ----------------
__global__ void __launch_bounds__(256) chunk_state_kernel(
    const float* __restrict__ xbc, const __half* __restrict__ zx,
    const float* __restrict__ dtb, const float* __restrict__ alog,
    float* __restrict__ sloc, float* __restrict__ cdecay, int rev)
{
    int c = blockIdx.x, head = blockIdx.y, b = blockIdx.z;
    int tid = threadIdx.x;
    __shared__ float Xs[CQ][HD + 4];
    __shared__ float Bs[CQ][DS + 1];
    __shared__ float Ls[CQ];
    __shared__ float wdt[CQ];
    size_t tbase = (size_t)b * T;
    float A = -expf(alog[head]);

    // Xs: 64 rows x 64 floats, float4 vectorized (16 float4 per row -> 1024 float4)
    for (int i = tid; i < CQ * 16; i += 256) {
        int j = i >> 4, q = i & 15;
        int s = c * CQ + j;
        int t = rev ? (T - 1 - s) : s;
        float4 v = *(const float4*)(xbc + (tbase + t) * CONVD + head * HD + q * 4);
        Xs[j][q * 4 + 0] = v.x; Xs[j][q * 4 + 1] = v.y;
        Xs[j][q * 4 + 2] = v.z; Xs[j][q * 4 + 3] = v.w;
    }
    // Bs: 64 rows x 16 floats (4 float4 per row)
    for (int i = tid; i < CQ * 4; i += 256) {
        int j = i >> 2, q = i & 3;
        int s = c * CQ + j;
        int t = rev ? (T - 1 - s) : s;
        float4 v = *(const float4*)(xbc + (tbase + t) * CONVD + DI + q * 4);
        Bs[j][q * 4 + 0] = v.x; Bs[j][q * 4 + 1] = v.y;
        Bs[j][q * 4 + 2] = v.z; Bs[j][q * 4 + 3] = v.w;
    }
    if (tid < CQ) {
        int s = c * CQ + tid;
        int t = rev ? (T - 1 - s) : s;
        float raw = __half2float(zx[(tbase + t) * DPROJ + (DI + CONVD) + head]) + dtb[head];
        float d = (raw > 20.f) ? raw : log1pf(expf(raw));
        wdt[tid] = d;
        Ls[tid] = d * A;
    }
    __syncthreads();
    for (int off = 1; off < CQ; off <<= 1) {
        float v = 0.f;
        if (tid < CQ) v = Ls[tid] + ((tid >= off) ? Ls[tid - off] : 0.f);
        __syncthreads();
        if (tid < CQ) Ls[tid] = v;
        __syncthreads();
    }
    float Lend = Ls[CQ - 1];

    int p = tid >> 2, ng = (tid & 3) << 2;
    float acc0 = 0.f, acc1 = 0.f, acc2 = 0.f, acc3 = 0.f;
    for (int j = 0; j < CQ; j++) {
        float w = expf(Lend - Ls[j]) * wdt[j];
        float xv = w * Xs[j][p];
        acc0 += xv * Bs[j][ng + 0];
        acc1 += xv * Bs[j][ng + 1];
        acc2 += xv * Bs[j][ng + 2];
        acc3 += xv * Bs[j][ng + 3];
    }
    size_t o = ((((size_t)b * NH + head) * NC + c) * HD + p) * DS + ng;
    sloc[o + 0] = acc0; sloc[o + 1] = acc1; sloc[o + 2] = acc2; sloc[o + 3] = acc3;
    if (tid == 0) cdecay[((size_t)b * NH + head) * NC + c] = expf(Lend);
}

__global__ void __launch_bounds__(256) chunk_scan_state(
    const float* __restrict__ sloc, const float* __restrict__ cdecay,
    float* __restrict__ hinit)
{
    int bh = blockIdx.x;
    int tid = threadIdx.x;
    float h0 = 0.f, h1 = 0.f, h2 = 0.f, h3 = 0.f;
    for (int c = 0; c < NC; c++) {
        size_t base = ((size_t)bh * NC + c) * (HD * DS);
        float d = cdecay[(size_t)bh * NC + c];
        size_t i0 = base + tid, i1 = base + tid + 256, i2 = base + tid + 512, i3 = base + tid + 768;
        hinit[i0] = h0; hinit[i1] = h1; hinit[i2] = h2; hinit[i3] = h3;
        h0 = d * h0 + sloc[i0];
        h1 = d * h1 + sloc[i1];
        h2 = d * h2 + sloc[i2];
        h3 = d * h3 + sloc[i3];
    }
}

__global__ void __launch_bounds__(256) chunk_output_kernel(
    const float* __restrict__ xbc, const __half* __restrict__ zx,
    const float* __restrict__ dtb, const float* __restrict__ alog,
    const float* __restrict__ hinit, const float* __restrict__ Dp,
    float* __restrict__ y, int rev)
{
    int c = blockIdx.x, head = blockIdx.y, b = blockIdx.z;
    int tid = threadIdx.x;
    __shared__ float Xs[CQ][HD + 4];
    __shared__ float Bs[CQ][DS + 1];
    __shared__ float Cs[CQ][DS + 1];
    __shared__ float h0s[HD][DS + 1];
    __shared__ float Ls[CQ];
    __shared__ float wdt[CQ];
    __shared__ float Ss[CQ][CQ + 1];
    size_t tbase = (size_t)b * T;
    float A = -expf(alog[head]);

    for (int i = tid; i < CQ * 16; i += 256) {
        int j = i >> 4, q = i & 15;
        int s = c * CQ + j;
        int t = rev ? (T - 1 - s) : s;
        float4 v = *(const float4*)(xbc + (tbase + t) * CONVD + head * HD + q * 4);
        Xs[j][q * 4 + 0] = v.x; Xs[j][q * 4 + 1] = v.y;
        Xs[j][q * 4 + 2] = v.z; Xs[j][q * 4 + 3] = v.w;
    }
    // B and C: 8 float4 per row (4 for B, 4 for C), contiguous in xbc
    for (int i = tid; i < CQ * 8; i += 256) {
        int j = i >> 3, q = i & 7;
        int s = c * CQ + j;
        int t = rev ? (T - 1 - s) : s;
        float4 v = *(const float4*)(xbc + (tbase + t) * CONVD + DI + q * 4);
        if (q < 4) {
            Bs[j][q * 4 + 0] = v.x; Bs[j][q * 4 + 1] = v.y;
            Bs[j][q * 4 + 2] = v.z; Bs[j][q * 4 + 3] = v.w;
        } else {
            int n = (q - 4) * 4;
            Cs[j][n + 0] = v.x; Cs[j][n + 1] = v.y;
            Cs[j][n + 2] = v.z; Cs[j][n + 3] = v.w;
        }
    }
    {
        size_t hb = ((((size_t)b * NH + head) * NC + c) * HD) * DS;
        for (int i = tid; i < HD * DS / 4; i += 256) {
            float4 v = *(const float4*)(hinit + hb + i * 4);
            int p = (i * 4) >> 4, n = (i * 4) & 15;
            h0s[p][n + 0] = v.x; h0s[p][n + 1] = v.y;
            h0s[p][n + 2] = v.z; h0s[p][n + 3] = v.w;
        }
    }
    if (tid < CQ) {
        int s = c * CQ + tid;
        int t = rev ? (T - 1 - s) : s;
        float raw = __half2float(zx[(tbase + t) * DPROJ + (DI + CONVD) + head]) + dtb[head];
        float d = (raw > 20.f) ? raw : log1pf(expf(raw));
        wdt[tid] = d;
        Ls[tid] = d * A;
    }
    __syncthreads();
    for (int off = 1; off < CQ; off <<= 1) {
        float v = 0.f;
        if (tid < CQ) v = Ls[tid] + ((tid >= off) ? Ls[tid - off] : 0.f);
        __syncthreads();
        if (tid < CQ) Ls[tid] = v;
        __syncthreads();
    }

    int t = tid >> 2;
    int quad = tid & 3;
    float Ct[DS];
#pragma unroll
    for (int n = 0; n < DS; n++) Ct[n] = Cs[t][n];
    float Lt = Ls[t];

    int jb = quad * 16;
#pragma unroll
    for (int q = 0; q < 16; q++) {
        int j = jb + q;
        float sv = 0.f;
        if (j <= t) {
            float dot = 0.f;
#pragma unroll
            for (int n = 0; n < DS; n++) dot += Ct[n] * Bs[j][n];
            sv = expf(Lt - Ls[j]) * wdt[j] * dot;
        }
        Ss[t][j] = sv;
    }
    __syncthreads();

    int pb = quad * 16;
    float acc[16];
#pragma unroll
    for (int k = 0; k < 16; k++) acc[k] = 0.f;
    for (int j = 0; j <= t; j++) {
        float sv = Ss[t][j];
#pragma unroll
        for (int k4 = 0; k4 < 4; k4++) {
            float4 xv = *(const float4*)&Xs[j][pb + k4 * 4];
            acc[k4 * 4 + 0] += sv * xv.x;
            acc[k4 * 4 + 1] += sv * xv.y;
            acc[k4 * 4 + 2] += sv * xv.z;
            acc[k4 * 4 + 3] += sv * xv.w;
        }
    }
    float et = expf(Lt);
    float Dv = Dp[head];
#pragma unroll
    for (int k = 0; k < 16; k++) {
        int p = pb + k;
        float dot = 0.f;
#pragma unroll
        for (int n = 0; n < DS; n++) dot += Ct[n] * h0s[p][n];
        acc[k] += et * dot + Dv * Xs[t][p];
    }
    int s_idx = c * CQ + t;
    int trow = rev ? (T - 1 - s_idx) : s_idx;
    float* yr = y + (tbase + trow) * DI + head * HD + pb;
#pragma unroll
    for (int k4 = 0; k4 < 4; k4++) {
        *(float4*)(yr + k4 * 4) = make_float4(acc[k4 * 4 + 0], acc[k4 * 4 + 1], acc[k4 * 4 + 2], acc[k4 * 4 + 3]);
    }
}

// ---------------- y = y * silu(z); RMSNorm(y) * gw -> fp16 (vectorized) ----------------
__global__ void gate_rms(const __half* __restrict__ zx, const float* __restrict__ y,
                         const float* __restrict__ gw, __half* __restrict__ yh) {
    int row = blockIdx.x;
    const __half* z = zx + (size_t)row * DPROJ;
    const float* yr = y + (size_t)row * DI;
    __half* yo = yh + (size_t)row * DI;
    int tid = threadIdx.x;   // 256; each handles 4 consecutive elements
    float4 yv = ((const float4*)yr)[tid];
    __half2 z01 = ((const __half2*)z)[2 * tid];
    __half2 z23 = ((const __half2*)z)[2 * tid + 1];
    float z0 = __half2float(z01.x), z1 = __half2float(z01.y);
    float z2 = __half2float(z23.x), z3 = __half2float(z23.y);
    float v0 = yv.x * (z0 / (1.f + expf(-z0)));
    float v1 = yv.y * (z1 / (1.f + expf(-z1)));
    float v2 = yv.z * (z2 / (1.f + expf(-z2)));
    float v3 = yv.w * (z3 / (1.f + expf(-z3)));
    float s2 = v0 * v0 + v1 * v1 + v2 * v2 + v3 * v3;
#pragma unroll
    for (int o = 16; o > 0; o >>= 1) s2 += __shfl_xor_sync(0xffffffffu, s2, o);
    __shared__ float rs[8];
    int wid = tid >> 5;
    if ((tid & 31) == 0) rs[wid] = s2;
    __syncthreads();
    float tot = 0.f;
#pragma unroll
    for (int i = 0; i < 8; i++) tot += rs[i];
    float inv = rsqrtf(tot * (1.f / DI) + 1e-5f);
    float4 gv = ((const float4*)gw)[tid];
    ((__half2*)yo)[2 * tid]     = __floats2half2_rn(v0 * inv * gv.x, v1 * inv * gv.y);
    ((__half2*)yo)[2 * tid + 1] = __floats2half2_rn(v2 * inv * gv.z, v3 * inv * gv.w);
}

// ---------------- host ----------------
static void* sym_addr_v(const void* sym) {
    void* p = nullptr;
    cudaGetSymbolAddress(&p, sym);
    return p;
}

extern "C" void kernel_launch(void* const* d_in, const int* in_sizes, int n_in,
                              void* d_out, int out_size) {
    const float* in_x   = (const float*)d_in[0];
    const float* n1w    = (const float*)d_in[1];
    const float* n1b    = (const float*)d_in[2];
    const float* inw    = (const float*)d_in[3];
    const float* cw     = (const float*)d_in[4];
    const float* cb     = (const float*)d_in[5];
    const float* dtb    = (const float*)d_in[6];
    const float* alog   = (const float*)d_in[7];
    const float* Dp     = (const float*)d_in[8];
    const float* gw     = (const float*)d_in[9];
    const float* ow     = (const float*)d_in[10];
    const float* n2w    = (const float*)d_in[11];
    const float* n2b    = (const float*)d_in[12];
    const float* f1w    = (const float*)d_in[13];
    const float* f2w    = (const float*)d_in[14];
    const float* nfw    = (const float*)d_in[15];
    const float* nfb    = (const float*)d_in[16];

    float*  resid = (float*) sym_addr_v(g_resid);
    __half* hh    = (__half*)sym_addr_v(g_hh);
    __half* zx    = (__half*)sym_addr_v(g_zx);
    float*  xbc   = (float*) sym_addr_v(g_xbc);
    float*  ybuf  = (float*) sym_addr_v(g_y);
    __half* yh    = (__half*)sym_addr_v(g_yh);
    float*  tmp   = (float*) sym_addr_v(g_tmp);
    __half* gluh  = (__half*)sym_addr_v(g_gluh);
    float*  xb    = (float*) sym_addr_v(g_x);
    float*  sloc  = (float*) sym_addr_v(g_sloc);
    float*  hinit = (float*) sym_addr_v(g_hinit);
    float*  cdec  = (float*) sym_addr_v(g_cdecay);
    __half* winw  = (__half*)sym_addr_v(g_winw);
    __half* wow   = (__half*)sym_addr_v(g_wow);
    __half* wf1   = (__half*)sym_addr_v(g_wf1);
    __half* wf2   = (__half*)sym_addr_v(g_wf2);

    static int smem_set = 0;
    if (!smem_set) {
        cudaFuncSetAttribute(h16_gemm_nt, cudaFuncAttributeMaxDynamicSharedMemorySize, GEMM_SMEM);
        smem_set = 1;
    }

    // convert all weights to fp16 in one launch
    conv_all_weights<<<(N4_ALL + 255) / 256, 256>>>(inw, ow, f1w, f2w, winw, wow, wf1, wf2);

    for (int i = 0; i < 4; i++) {
        int rev = i & 1;
        const float* xin = (i == 0) ? in_x : xb;

        add_ln_kernel<<<ROWS / 2, 256>>>(xin, resid, n1w + i * DM, n1b + i * DM, hh, (i == 0) ? 1 : 0, 1);

        {   // in_proj [8192 x 2096 x 512] -> zx fp16
            dim3 grid((DPROJ + 127) / 128, ROWS / 128);
            h16_gemm_nt<<<grid, 256, GEMM_SMEM>>>(ROWS, DPROJ, DM, hh, winw + (size_t)i * DPROJ * DM, zx, 2);
        }

        conv_silu<<<((ROWS / 4) * CONVD + 255) / 256, 256>>>(zx, cw + (size_t)i * CONVD * 4, cb + i * CONVD, xbc, rev);

        {
            dim3 gs(NC, NH, BATCH);
            chunk_state_kernel<<<gs, 256>>>(xbc, zx, dtb + i * NH, alog + i * NH, sloc, cdec, rev);
            chunk_scan_state<<<BATCH * NH, 256>>>(sloc, cdec, hinit);
            chunk_output_kernel<<<gs, 256>>>(xbc, zx, dtb + i * NH, alog + i * NH, hinit, Dp + i * NH, ybuf, rev);
        }

        gate_rms<<<ROWS, 256>>>(zx, ybuf, gw + i * DI, yh);

        {   // out_proj [8192 x 512 x 1024]
            dim3 grid(DM / 128, ROWS / 128);
            h16_gemm_nt<<<grid, 256, GEMM_SMEM>>>(ROWS, DM, DI, yh, wow + (size_t)i * DM * DI, tmp, 0);
        }

        add_ln_kernel<<<ROWS / 2, 256>>>(tmp, resid, n2w + i * DM, n2b + i * DM, hh, 0, 1);

        {   // FFN f1 + fused GLU
            dim3 grid(DM / 128, ROWS / 128);
            h16_gemm_nt<<<grid, 256, GEMM_SMEM>>>(ROWS, DM, DM, hh, wf1 + (size_t)i * DM * DM, gluh, 1);
        }

        {   // FFN f2 [8192 x 512 x 256]
            dim3 grid(DM / 128, ROWS / 128);
            h16_gemm_nt<<<grid, 256, GEMM_SMEM>>>(ROWS, DM, DINTER, gluh, wf2 + (size_t)i * DM * DINTER, xb, 0);
        }
    }

    add_ln_kernel<<<ROWS / 2, 256>>>(xb, resid, nfw, nfb, (float*)d_out, 0, 0);
}

// round 16
// speedup vs baseline: 1.2231x; 1.0430x over previous
#include <cuda_runtime.h>
#include <cuda_fp16.h>
#include <math.h>
#include <stdint.h>

#define BATCH 4
#define T 2048
#define DM 512
#define DI 1024
#define NH 16
#define HD 64
#define DS 16
#define CONVD 1056
#define DPROJ 2096
#define DINTER 256
#define ROWS (BATCH*T)

// chunked scan
#define CQ 64
#define NC (T/CQ)

// fp16 GEMM tiling: block 128(M) x 128(N), BK=64 halves, 3 stages, 2 CTAs/SM
#define BKH 64
#define LDA 72
#define A_ST_BYTES (128*144)
#define B_ST_BYTES (128*144)
#define ST_BYTES (A_ST_BYTES+B_ST_BYTES)
#define STG 3
#define GEMM_SMEM (STG*ST_BYTES)    // 110592

// ---------------- scratch ----------------
__device__ float g_resid[ROWS*DM];
__device__ __half g_hh[ROWS*DM];
__device__ __half g_zx[ROWS*DPROJ];
__device__ __half g_xbc[ROWS*CONVD];      // fp16 now
__device__ float g_y[ROWS*DI];
__device__ __half g_yh[ROWS*DI];
__device__ float g_tmp[ROWS*DM];
__device__ __half g_gluh[ROWS*DINTER];
__device__ float g_x[ROWS*DM];
__device__ float g_sloc[BATCH*NH*NC*HD*DS];
__device__ float g_hinit[BATCH*NH*NC*HD*DS];
__device__ float g_cdecay[BATCH*NH*NC];
// fp16 weights
__device__ __half g_winw[4*DPROJ*DM];
__device__ __half g_wow[4*DM*DI];
__device__ __half g_wf1[4*2*DINTER*DM];
__device__ __half g_wf2[4*DM*DINTER];

// ---------------- fused weight conversion ----------------
#define N4_INW (4*DPROJ*DM/4)
#define N4_OW  (4*DM*DI/4)
#define N4_F1  (4*2*DINTER*DM/4)
#define N4_F2  (4*DM*DINTER/4)
#define N4_ALL (N4_INW+N4_OW+N4_F1+N4_F2)

__global__ void conv_all_weights(const float* __restrict__ inw, const float* __restrict__ ow,
                                 const float* __restrict__ f1w, const float* __restrict__ f2w,
                                 __half* __restrict__ winw, __half* __restrict__ wow,
                                 __half* __restrict__ wf1, __half* __restrict__ wf2) {
    int i = blockIdx.x * blockDim.x + threadIdx.x;
    if (i >= N4_ALL) return;
    const float* src; __half* dst; int li;
    if (i < N4_INW) { src = inw; dst = winw; li = i; }
    else if (i < N4_INW + N4_OW) { src = ow; dst = wow; li = i - N4_INW; }
    else if (i < N4_INW + N4_OW + N4_F1) {
        int j = i - N4_INW - N4_OW;
        float4 v = ((const float4*)f1w)[j];
        int k4 = j & 127;
        int row = (j >> 7) & 511;
        int l = j >> 16;
        int drow = (row < 256) ? (2 * row) : (2 * (row - 256) + 1);
        size_t o = (((size_t)l * 512 + drow) * 512 + k4 * 4);
        ((__half2*)(wf1 + o))[0] = __floats2half2_rn(v.x, v.y);
        ((__half2*)(wf1 + o))[1] = __floats2half2_rn(v.z, v.w);
        return;
    }
    else { src = f2w; dst = wf2; li = i - N4_INW - N4_OW - N4_F1; }
    float4 v = ((const float4*)src)[li];
    ((__half2*)dst)[2 * li]     = __floats2half2_rn(v.x, v.y);
    ((__half2*)dst)[2 * li + 1] = __floats2half2_rn(v.z, v.w);
}

// ---------------- residual add + LayerNorm (2 rows/block, float4) ----------------
__global__ void add_ln_kernel(const float* __restrict__ xin, float* __restrict__ resid,
                              const float* __restrict__ w, const float* __restrict__ bch,
                              void* __restrict__ out, int first, int to_half) {
    int row = blockIdx.x * 2 + (threadIdx.x >> 7);
    int tid = threadIdx.x & 127;
    int half_id = threadIdx.x >> 7;
    const float* xr = xin + (size_t)row * DM;
    float* rr = resid + (size_t)row * DM;
    float4 v = ((const float4*)xr)[tid];
    if (!first) {
        float4 r = ((const float4*)rr)[tid];
        v.x += r.x; v.y += r.y; v.z += r.z; v.w += r.w;
    }
    float s = v.x + v.y + v.z + v.w;
    float s2 = v.x * v.x + v.y * v.y + v.z * v.z + v.w * v.w;
#pragma unroll
    for (int o = 16; o > 0; o >>= 1) {
        s  += __shfl_xor_sync(0xffffffffu, s, o);
        s2 += __shfl_xor_sync(0xffffffffu, s2, o);
    }
    __shared__ float rs[8], rs2[8];
    int wid = threadIdx.x >> 5;
    if ((threadIdx.x & 31) == 0) { rs[wid] = s; rs2[wid] = s2; }
    __syncthreads();
    int wb = half_id * 4;
    float tot  = rs[wb] + rs[wb + 1] + rs[wb + 2] + rs[wb + 3];
    float tot2 = rs2[wb] + rs2[wb + 1] + rs2[wb + 2] + rs2[wb + 3];
    float mu = tot * (1.f / DM);
    float var = tot2 * (1.f / DM) - mu * mu;
    float inv = rsqrtf(var + 1e-5f);
    ((float4*)rr)[tid] = v;
    float4 wv = ((const float4*)w)[tid];
    float4 bv = ((const float4*)bch)[tid];
    float o0 = (v.x - mu) * inv * wv.x + bv.x;
    float o1 = (v.y - mu) * inv * wv.y + bv.y;
    float o2 = (v.z - mu) * inv * wv.z + bv.z;
    float o3 = (v.w - mu) * inv * wv.w + bv.w;
    if (to_half) {
        __half2* op = (__half2*)((__half*)out + (size_t)row * DM);
        op[2 * tid]     = __floats2half2_rn(o0, o1);
        op[2 * tid + 1] = __floats2half2_rn(o2, o3);
    } else {
        ((float4*)((float*)out + (size_t)row * DM))[tid] = make_float4(o0, o1, o2, o3);
    }
}

// ---------------- fp16 tensor-core NT GEMM (128x128, 3-stage, 2 CTA/SM) ----------------
#define MMA_F16(d, a, b) \
    asm volatile("mma.sync.aligned.m16n8k16.row.col.f32.f16.f16.f32 " \
                 "{%0,%1,%2,%3},{%4,%5,%6,%7},{%8,%9},{%0,%1,%2,%3};" \
                 : "+f"(d[0]), "+f"(d[1]), "+f"(d[2]), "+f"(d[3]) \
                 : "r"(a[0]), "r"(a[1]), "r"(a[2]), "r"(a[3]), "r"(b[0]), "r"(b[1]))

#define LDSM_X4(R, addr) \
    asm volatile("ldmatrix.sync.aligned.m8n8.x4.shared.b16 {%0,%1,%2,%3}, [%4];" \
                 : "=r"((R)[0]), "=r"((R)[1]), "=r"((R)[2]), "=r"((R)[3]) : "r"(addr))

__device__ __forceinline__ void gemm_load_stage(
    const __half* __restrict__ A, const __half* __restrict__ Bw,
    int K, int N, int bm, int bn, int it, int s, int tid, uint32_t sbase)
{
    int k0 = it * BKH;
    uint32_t stA = sbase + (uint32_t)s * ST_BYTES;
    uint32_t stB = stA + A_ST_BYTES;
#pragma unroll
    for (int i = 0; i < 4; i++) {
        int idx = i * 256 + tid;
        int row = idx >> 3, c = idx & 7;
        uint32_t dst = stA + (uint32_t)row * 144u + (uint32_t)(c << 4);
        const __half* gp = A + (size_t)(bm + row) * K + k0 + c * 8;
        asm volatile("cp.async.cg.shared.global [%0], [%1], 16;" :: "r"(dst), "l"(gp));
    }
#pragma unroll
    for (int i = 0; i < 4; i++) {
        int idx = i * 256 + tid;
        int row = idx >> 3, c = idx & 7;
        int rb = bn + row;
        int valid = (rb < N);
        uint32_t dst = stB + (uint32_t)row * 144u + (uint32_t)(c << 4);
        const __half* gp = Bw + (size_t)(valid ? rb : 0) * K + k0 + c * 8;
        int ssz = valid ? 16 : 0;
        asm volatile("cp.async.cg.shared.global [%0], [%1], 16, %2;" :: "r"(dst), "l"(gp), "r"(ssz));
    }
    asm volatile("cp.async.commit_group;" ::: "memory");
}

// out_mode: 0 = fp32 C, 1 = fused GLU (fp16, N/2 cols), 2 = fp16 C
__global__ void __launch_bounds__(256, 2) h16_gemm_nt(int M, int N, int K,
                                                      const __half* __restrict__ A,
                                                      const __half* __restrict__ Bw,
                                                      void* __restrict__ Cv, int out_mode) {
    extern __shared__ char smem[];
    uint32_t sbase = (uint32_t)__cvta_generic_to_shared(smem);
    int bm = blockIdx.y * 128, bn = blockIdx.x * 128;
    int tid = threadIdx.x;
    int wid = tid >> 5, lane = tid & 31;
    int wm = (wid & 1) * 64;
    int wn = (wid >> 1) * 32;
    int g = lane >> 2, tig = lane & 3;

    int arow = lane & 15;
    int acol = (lane >> 4) << 3;
    int brow = ((lane >> 4) << 3) + (lane & 7);
    int bcol = ((lane >> 3) & 1) << 3;
    uint32_t aoff = ((uint32_t)((wm + arow) * LDA + acol)) * 2u;
    uint32_t boff = ((uint32_t)((wn + brow) * LDA + bcol)) * 2u + A_ST_BYTES;

    float acc[4][4][4];
#pragma unroll
    for (int i = 0; i < 4; i++)
#pragma unroll
        for (int j = 0; j < 4; j++)
#pragma unroll
            for (int k = 0; k < 4; k++) acc[i][j][k] = 0.f;

    int NIT = K / BKH;
#pragma unroll
    for (int p = 0; p < STG - 1; p++)
        if (p < NIT) gemm_load_stage(A, Bw, K, N, bm, bn, p, p, tid, sbase);

    for (int it = 0; it < NIT; ++it) {
        int pend = NIT - it - 1; if (pend > STG - 2) pend = STG - 2;
        if (pend == 1) asm volatile("cp.async.wait_group 1;" ::: "memory");
        else           asm volatile("cp.async.wait_group 0;" ::: "memory");
        __syncthreads();

        int ld = it + STG - 1;
        if (ld < NIT) gemm_load_stage(A, Bw, K, N, bm, bn, ld, ld % STG, tid, sbase);

        int s = it % STG;
        uint32_t Ab = sbase + (uint32_t)s * ST_BYTES + aoff;
        uint32_t Bb = sbase + (uint32_t)s * ST_BYTES + boff;
#pragma unroll
        for (int ks = 0; ks < 4; ks++) {
            uint32_t kbyte = (uint32_t)(ks * 16 * 2);
            uint32_t a[4][4], b[2][4];
#pragma unroll
            for (int mt = 0; mt < 4; mt++)
                LDSM_X4(a[mt], Ab + (uint32_t)(mt * 16 * LDA) * 2u + kbyte);
#pragma unroll
            for (int np = 0; np < 2; np++)
                LDSM_X4(b[np], Bb + (uint32_t)(np * 16 * LDA) * 2u + kbyte);
#pragma unroll
            for (int mt = 0; mt < 4; mt++)
#pragma unroll
                for (int np = 0; np < 2; np++) {
                    MMA_F16(acc[mt][2 * np], a[mt], b[np]);
                    uint32_t bhi[2] = { b[np][2], b[np][3] };
                    MMA_F16(acc[mt][2 * np + 1], a[mt], bhi);
                }
        }
    }

    if (out_mode == 0) {
        float* C = (float*)Cv;
#pragma unroll
        for (int mt = 0; mt < 4; mt++) {
            int r0 = bm + wm + mt * 16 + g;
#pragma unroll
            for (int nt = 0; nt < 4; nt++) {
                int c0 = bn + wn + nt * 8 + tig * 2;
                if (c0 < N) {
                    *(float2*)&C[(size_t)r0 * N + c0] = make_float2(acc[mt][nt][0], acc[mt][nt][1]);
                    *(float2*)&C[(size_t)(r0 + 8) * N + c0] = make_float2(acc[mt][nt][2], acc[mt][nt][3]);
                }
            }
        }
    } else if (out_mode == 2) {
        __half* C = (__half*)Cv;
#pragma unroll
        for (int mt = 0; mt < 4; mt++) {
            int r0 = bm + wm + mt * 16 + g;
#pragma unroll
            for (int nt = 0; nt < 4; nt++) {
                int c0 = bn + wn + nt * 8 + tig * 2;
                if (c0 < N) {
                    *(__half2*)&C[(size_t)r0 * N + c0] = __floats2half2_rn(acc[mt][nt][0], acc[mt][nt][1]);
                    *(__half2*)&C[(size_t)(r0 + 8) * N + c0] = __floats2half2_rn(acc[mt][nt][2], acc[mt][nt][3]);
                }
            }
        }
    } else {
        __half* C = (__half*)Cv;
        int No = N >> 1;
#pragma unroll
        for (int mt = 0; mt < 4; mt++) {
            int r0 = bm + wm + mt * 16 + g;
#pragma unroll
            for (int nt = 0; nt < 4; nt++) {
                int c0 = bn + wn + nt * 8 + tig * 2;
                if (c0 < N) {
                    float a0 = acc[mt][nt][0], g0 = acc[mt][nt][1];
                    float a1 = acc[mt][nt][2], g1 = acc[mt][nt][3];
                    C[(size_t)r0 * No + (c0 >> 1)] = __float2half_rn(a0 * g0 / (1.f + expf(-g0)));
                    C[(size_t)(r0 + 8) * No + (c0 >> 1)] = __float2half_rn(a1 * g1 / (1.f + expf(-g1)));
                }
            }
        }
    }
}

// ---------------- depthwise conv: 2 channels x 4 t-steps per thread, fp16 in/out ----------------
#define CPAIRS (CONVD/2)
__global__ void conv_silu(const __half* __restrict__ zx, const float* __restrict__ cw,
                          const float* __restrict__ cb, __half* __restrict__ out, int rev) {
    int idx = blockIdx.x * blockDim.x + threadIdx.x;
    if (idx >= (ROWS / 4) * CPAIRS) return;
    int c2 = idx % CPAIRS; int tt = idx / CPAIRS;
    int b = tt / (T / 4); int t0 = (tt % (T / 4)) * 4;
    int c = 2 * c2;
    float4 w0 = *(const float4*)(cw + c * 4);
    float4 w1 = *(const float4*)(cw + (c + 1) * 4);
    float b0 = cb[c], b1 = cb[c + 1];
    const __half2* col = (const __half2*)(zx + (size_t)b * T * DPROJ + DI + c);
    float2 win[7];
    if (!rev) {
#pragma unroll
        for (int j = 0; j < 7; j++) {
            int t = t0 - 3 + j;
            win[j] = (t >= 0) ? __half22float2(col[(size_t)t * (DPROJ / 2)]) : make_float2(0.f, 0.f);
        }
#pragma unroll
        for (int i = 0; i < 4; i++) {
            float a0 = b0 + w0.x * win[i].x + w0.y * win[i + 1].x + w0.z * win[i + 2].x + w0.w * win[i + 3].x;
            float a1 = b1 + w1.x * win[i].y + w1.y * win[i + 1].y + w1.z * win[i + 2].y + w1.w * win[i + 3].y;
            float o0 = a0 / (1.f + expf(-a0));
            float o1 = a1 / (1.f + expf(-a1));
            ((__half2*)(out + ((size_t)b * T + t0 + i) * CONVD + c))[0] = __floats2half2_rn(o0, o1);
        }
    } else {
#pragma unroll
        for (int j = 0; j < 7; j++) {
            int t = t0 + j;
            win[j] = (t < T) ? __half22float2(col[(size_t)t * (DPROJ / 2)]) : make_float2(0.f, 0.f);
        }
#pragma unroll
        for (int i = 0; i < 4; i++) {
            float a0 = b0 + w0.w * win[i].x + w0.z * win[i + 1].x + w0.y * win[i + 2].x + w0.x * win[i + 3].x;
            float a1 = b1 + w1.w * win[i].y + w1.z * win[i + 1].y + w1.y * win[i + 2].y + w1.x * win[i + 3].y;
            float o0 = a0 / (1.f + expf(-a0));
            float o1 = a1 / (1.f + expf(-a1));
            ((__half2*)(out + ((size_t)b * T + t0 + i) * CONVD + c))[0] = __floats2half2_rn(o0, o1);
        }
    }
}

// unpack 8 halves (uint4) into floats
__device__ __forceinline__ void unpack8(uint4 u, float* dst) {
    __half2* h = (__half2*)&u;
#pragma unroll
    for (int k = 0; k < 4; k++) {
        float2 f = __half22float2(h[k]);
        dst[2 * k] = f.x; dst[2 * k + 1] = f.y;
    }
}

// ---------------- chunked SSD scan (xbc fp16, dt inline from zx) ----------------
__global__ void __launch_bounds__(256) chunk_state_kernel(
    const __half* __restrict__ xbc, const __half* __restrict__ zx,
    const float* __restrict__ dtb, const float* __restrict__ alog,
    float* __restrict__ sloc, float* __restrict__ cdecay, int rev)
{
    int c = blockIdx.x, head = blockIdx.y, b = blockIdx.z;
    int tid = threadIdx.x;
    __shared__ float Xs[CQ][HD + 4];
    __shared__ float Bs[CQ][DS + 1];
    __shared__ float Ls[CQ];
    __shared__ float wdt[CQ];
    size_t tbase = (size_t)b * T;
    float A = -expf(alog[head]);

    // Xs: 64 rows x 64 halves -> 8 uint4 per row
    for (int i = tid; i < CQ * 8; i += 256) {
        int j = i >> 3, q = i & 7;
        int s = c * CQ + j;
        int t = rev ? (T - 1 - s) : s;
        uint4 u = *(const uint4*)(xbc + (tbase + t) * CONVD + head * HD + q * 8);
        unpack8(u, &Xs[j][q * 8]);
    }
    // Bs: 16 halves -> 2 uint4 per row
    for (int i = tid; i < CQ * 2; i += 256) {
        int j = i >> 1, q = i & 1;
        int s = c * CQ + j;
        int t = rev ? (T - 1 - s) : s;
        uint4 u = *(const uint4*)(xbc + (tbase + t) * CONVD + DI + q * 8);
        unpack8(u, &Bs[j][q * 8]);
    }
    if (tid < CQ) {
        int s = c * CQ + tid;
        int t = rev ? (T - 1 - s) : s;
        float raw = __half2float(zx[(tbase + t) * DPROJ + (DI + CONVD) + head]) + dtb[head];
        float d = (raw > 20.f) ? raw : log1pf(expf(raw));
        wdt[tid] = d;
        Ls[tid] = d * A;
    }
    __syncthreads();
    for (int off = 1; off < CQ; off <<= 1) {
        float v = 0.f;
        if (tid < CQ) v = Ls[tid] + ((tid >= off) ? Ls[tid - off] : 0.f);
        __syncthreads();
        if (tid < CQ) Ls[tid] = v;
        __syncthreads();
    }
    float Lend = Ls[CQ - 1];

    int p = tid >> 2, ng = (tid & 3) << 2;
    float acc0 = 0.f, acc1 = 0.f, acc2 = 0.f, acc3 = 0.f;
    for (int j = 0; j < CQ; j++) {
        float w = expf(Lend - Ls[j]) * wdt[j];
        float xv = w * Xs[j][p];
        acc0 += xv * Bs[j][ng + 0];
        acc1 += xv * Bs[j][ng + 1];
        acc2 += xv * Bs[j][ng + 2];
        acc3 += xv * Bs[j][ng + 3];
    }
    size_t o = ((((size_t)b * NH + head) * NC + c) * HD + p) * DS + ng;
    sloc[o + 0] = acc0; sloc[o + 1] = acc1; sloc[o + 2] = acc2; sloc[o + 3] = acc3;
    if (tid == 0) cdecay[((size_t)b * NH + head) * NC + c] = expf(Lend);
}

__global__ void __launch_bounds__(256) chunk_scan_state(
    const float* __restrict__ sloc, const float* __restrict__ cdecay,
    float* __restrict__ hinit)
{
    int bh = blockIdx.x;
    int tid = threadIdx.x;
    float h0 = 0.f, h1 = 0.f, h2 = 0.f, h3 = 0.f;
    for (int c = 0; c < NC; c++) {
        size_t base = ((size_t)bh * NC + c) * (HD * DS);
        float d = cdecay[(size_t)bh * NC + c];
        size_t i0 = base + tid, i1 = base + tid + 256, i2 = base + tid + 512, i3 = base + tid + 768;
        hinit[i0] = h0; hinit[i1] = h1; hinit[i2] = h2; hinit[i3] = h3;
        h0 = d * h0 + sloc[i0];
        h1 = d * h1 + sloc[i1];
        h2 = d * h2 + sloc[i2];
        h3 = d * h3 + sloc[i3];
    }
}

__global__ void __launch_bounds__(256) chunk_output_kernel(
    const __half* __restrict__ xbc, const __half* __restrict__ zx,
    const float* __restrict__ dtb, const float* __restrict__ alog,
    const float* __restrict__ hinit, const float* __restrict__ Dp,
    float* __restrict__ y, int rev)
{
    int c = blockIdx.x, head = blockIdx.y, b = blockIdx.z;
    int tid = threadIdx.x;
    __shared__ float Xs[CQ][HD + 4];
    __shared__ float Bs[CQ][DS + 1];
    __shared__ float Cs[CQ][DS + 1];
    __shared__ float h0s[HD][DS + 1];
    __shared__ float Ls[CQ];
    __shared__ float wdt[CQ];
    __shared__ float Ss[CQ][CQ + 1];
    size_t tbase = (size_t)b * T;
    float A = -expf(alog[head]);

    for (int i = tid; i < CQ * 8; i += 256) {
        int j = i >> 3, q = i & 7;
        int s = c * CQ + j;
        int t = rev ? (T - 1 - s) : s;
        uint4 u = *(const uint4*)(xbc + (tbase + t) * CONVD + head * HD + q * 8);
        unpack8(u, &Xs[j][q * 8]);
    }
    // B and C: 32 halves contiguous -> 4 uint4 per row
    for (int i = tid; i < CQ * 4; i += 256) {
        int j = i >> 2, q = i & 3;
        int s = c * CQ + j;
        int t = rev ? (T - 1 - s) : s;
        uint4 u = *(const uint4*)(xbc + (tbase + t) * CONVD + DI + q * 8);
        if (q < 2) unpack8(u, &Bs[j][q * 8]);
        else       unpack8(u, &Cs[j][(q - 2) * 8]);
    }
    {
        size_t hb = ((((size_t)b * NH + head) * NC + c) * HD) * DS;
        for (int i = tid; i < HD * DS / 4; i += 256) {
            float4 v = *(const float4*)(hinit + hb + i * 4);
            int p = (i * 4) >> 4, n = (i * 4) & 15;
            h0s[p][n + 0] = v.x; h0s[p][n + 1] = v.y;
            h0s[p][n + 2] = v.z; h0s[p][n + 3] = v.w;
        }
    }
    if (tid < CQ) {
        int s = c * CQ + tid;
        int t = rev ? (T - 1 - s) : s;
        float raw = __half2float(zx[(tbase + t) * DPROJ + (DI + CONVD) + head]) + dtb[head];
        float d = (raw > 20.f) ? raw : log1pf(expf(raw));
        wdt[tid] = d;
        Ls[tid] = d * A;
    }
    __syncthreads();
    for (int off = 1; off < CQ; off <<= 1) {
        float v = 0.f;
        if (tid < CQ) v = Ls[tid] + ((tid >= off) ? Ls[tid - off] : 0.f);
        __syncthreads();
        if (tid < CQ) Ls[tid] = v;
        __syncthreads();
    }

    int t = tid >> 2;
    int quad = tid & 3;
    float Ct[DS];
#pragma unroll
    for (int n = 0; n < DS; n++) Ct[n] = Cs[t][n];
    float Lt = Ls[t];

    int jb = quad * 16;
#pragma unroll
    for (int q = 0; q < 16; q++) {
        int j = jb + q;
        float sv = 0.f;
        if (j <= t) {
            float dot = 0.f;
#pragma unroll
            for (int n = 0; n < DS; n++) dot += Ct[n] * Bs[j][n];
            sv = expf(Lt - Ls[j]) * wdt[j] * dot;
        }
        Ss[t][j] = sv;
    }
    __syncthreads();

    int pb = quad * 16;
    float acc[16];
#pragma unroll
    for (int k = 0; k < 16; k++) acc[k] = 0.f;
    for (int j = 0; j <= t; j++) {
        float sv = Ss[t][j];
#pragma unroll
        for (int k4 = 0; k4 < 4; k4++) {
            float4 xv = *(const float4*)&Xs[j][pb + k4 * 4];
            acc[k4 * 4 + 0] += sv * xv.x;
            acc[k4 * 4 + 1] += sv * xv.y;
            acc[k4 * 4 + 2] += sv * xv.z;
            acc[k4 * 4 + 3] += sv * xv.w;
        }
    }
    float et = expf(Lt);
    float Dv = Dp[head];
#pragma unroll
    for (int k = 0; k < 16; k++) {
        int p = pb + k;
        float dot = 0.f;
#pragma unroll
        for (int n = 0; n < DS; n++) dot += Ct[n] * h0s[p][n];
        acc[k] += et * dot + Dv * Xs[t][p];
    }
    int s_idx = c * CQ + t;
    int trow = rev ? (T - 1 - s_idx) : s_idx;
    float* yr = y + (tbase + trow) * DI + head * HD + pb;
#pragma unroll
    for (int k4 = 0; k4 < 4; k4++) {
        *(float4*)(yr + k4 * 4) = make_float4(acc[k4 * 4 + 0], acc[k4 * 4 + 1], acc[k4 * 4 + 2], acc[k4 * 4 + 3]);
    }
}

// ---------------- y = y * silu(z); RMSNorm(y) * gw -> fp16 (vectorized) ----------------
__global__ void gate_rms(const __half* __restrict__ zx, const float* __restrict__ y,
                         const float* __restrict__ gw, __half* __restrict__ yh) {
    int row = blockIdx.x;
    const __half* z = zx + (size_t)row * DPROJ;
    const float* yr = y + (size_t)row * DI;
    __half* yo = yh + (size_t)row * DI;
    int tid = threadIdx.x;
    float4 yv = ((const float4*)yr)[tid];
    __half2 z01 = ((const __half2*)z)[2 * tid];
    __half2 z23 = ((const __half2*)z)[2 * tid + 1];
    float z0 = __half2float(z01.x), z1 = __half2float(z01.y);
    float z2 = __half2float(z23.x), z3 = __half2float(z23.y);
    float v0 = yv.x * (z0 / (1.f + expf(-z0)));
    float v1 = yv.y * (z1 / (1.f + expf(-z1)));
    float v2 = yv.z * (z2 / (1.f + expf(-z2)));
    float v3 = yv.w * (z3 / (1.f + expf(-z3)));
    float s2 = v0 * v0 + v1 * v1 + v2 * v2 + v3 * v3;
#pragma unroll
    for (int o = 16; o > 0; o >>= 1) s2 += __shfl_xor_sync(0xffffffffu, s2, o);
    __shared__ float rs[8];
    int wid = tid >> 5;
    if ((tid & 31) == 0) rs[wid] = s2;
    __syncthreads();
    float tot = 0.f;
#pragma unroll
    for (int i = 0; i < 8; i++) tot += rs[i];
    float inv = rsqrtf(tot * (1.f / DI) + 1e-5f);
    float4 gv = ((const float4*)gw)[tid];
    ((__half2*)yo)[2 * tid]     = __floats2half2_rn(v0 * inv * gv.x, v1 * inv * gv.y);
    ((__half2*)yo)[2 * tid + 1] = __floats2half2_rn(v2 * inv * gv.z, v3 * inv * gv.w);
}

// ---------------- host ----------------
static void* sym_addr_v(const void* sym) {
    void* p = nullptr;
    cudaGetSymbolAddress(&p, sym);
    return p;
}

extern "C" void kernel_launch(void* const* d_in, const int* in_sizes, int n_in,
                              void* d_out, int out_size) {
    const float* in_x   = (const float*)d_in[0];
    const float* n1w    = (const float*)d_in[1];
    const float* n1b    = (const float*)d_in[2];
    const float* inw    = (const float*)d_in[3];
    const float* cw     = (const float*)d_in[4];
    const float* cb     = (const float*)d_in[5];
    const float* dtb    = (const float*)d_in[6];
    const float* alog   = (const float*)d_in[7];
    const float* Dp     = (const float*)d_in[8];
    const float* gw     = (const float*)d_in[9];
    const float* ow     = (const float*)d_in[10];
    const float* n2w    = (const float*)d_in[11];
    const float* n2b    = (const float*)d_in[12];
    const float* f1w    = (const float*)d_in[13];
    const float* f2w    = (const float*)d_in[14];
    const float* nfw    = (const float*)d_in[15];
    const float* nfb    = (const float*)d_in[16];

    float*  resid = (float*) sym_addr_v(g_resid);
    __half* hh    = (__half*)sym_addr_v(g_hh);
    __half* zx    = (__half*)sym_addr_v(g_zx);
    __half* xbc   = (__half*)sym_addr_v(g_xbc);
    float*  ybuf  = (float*) sym_addr_v(g_y);
    __half* yh    = (__half*)sym_addr_v(g_yh);
    float*  tmp   = (float*) sym_addr_v(g_tmp);
    __half* gluh  = (__half*)sym_addr_v(g_gluh);
    float*  xb    = (float*) sym_addr_v(g_x);
    float*  sloc  = (float*) sym_addr_v(g_sloc);
    float*  hinit = (float*) sym_addr_v(g_hinit);
    float*  cdec  = (float*) sym_addr_v(g_cdecay);
    __half* winw  = (__half*)sym_addr_v(g_winw);
    __half* wow   = (__half*)sym_addr_v(g_wow);
    __half* wf1   = (__half*)sym_addr_v(g_wf1);
    __half* wf2   = (__half*)sym_addr_v(g_wf2);

    static int smem_set = 0;
    if (!smem_set) {
        cudaFuncSetAttribute(h16_gemm_nt, cudaFuncAttributeMaxDynamicSharedMemorySize, GEMM_SMEM);
        smem_set = 1;
    }

    conv_all_weights<<<(N4_ALL + 255) / 256, 256>>>(inw, ow, f1w, f2w, winw, wow, wf1, wf2);

    for (int i = 0; i < 4; i++) {
        int rev = i & 1;
        const float* xin = (i == 0) ? in_x : xb;

        add_ln_kernel<<<ROWS / 2, 256>>>(xin, resid, n1w + i * DM, n1b + i * DM, hh, (i == 0) ? 1 : 0, 1);

        {   // in_proj [8192 x 2096 x 512] -> zx fp16
            dim3 grid((DPROJ + 127) / 128, ROWS / 128);
            h16_gemm_nt<<<grid, 256, GEMM_SMEM>>>(ROWS, DPROJ, DM, hh, winw + (size_t)i * DPROJ * DM, zx, 2);
        }

        conv_silu<<<((ROWS / 4) * CPAIRS + 255) / 256, 256>>>(zx, cw + (size_t)i * CONVD * 4, cb + i * CONVD, xbc, rev);

        {
            dim3 gs(NC, NH, BATCH);
            chunk_state_kernel<<<gs, 256>>>(xbc, zx, dtb + i * NH, alog + i * NH, sloc, cdec, rev);
            chunk_scan_state<<<BATCH * NH, 256>>>(sloc, cdec, hinit);
            chunk_output_kernel<<<gs, 256>>>(xbc, zx, dtb + i * NH, alog + i * NH, hinit, Dp + i * NH, ybuf, rev);
        }

        gate_rms<<<ROWS, 256>>>(zx, ybuf, gw + i * DI, yh);

        {   // out_proj [8192 x 512 x 1024]
            dim3 grid(DM / 128, ROWS / 128);
            h16_gemm_nt<<<grid, 256, GEMM_SMEM>>>(ROWS, DM, DI, yh, wow + (size_t)i * DM * DI, tmp, 0);
        }

        add_ln_kernel<<<ROWS / 2, 256>>>(tmp, resid, n2w + i * DM, n2b + i * DM, hh, 0, 1);

        {   // FFN f1 + fused GLU
            dim3 grid(DM / 128, ROWS / 128);
            h16_gemm_nt<<<grid, 256, GEMM_SMEM>>>(ROWS, DM, DM, hh, wf1 + (size_t)i * DM * DM, gluh, 1);
        }

        {   // FFN f2 [8192 x 512 x 256]
            dim3 grid(DM / 128, ROWS / 128);
            h16_gemm_nt<<<grid, 256, GEMM_SMEM>>>(ROWS, DM, DINTER, gluh, wf2 + (size_t)i * DM * DINTER, xb, 0);
        }
    }

    add_ln_kernel<<<ROWS / 2, 256>>>(xb, resid, nfw, nfb, (float*)d_out, 0, 0);
}